// round 13
// baseline (speedup 1.0000x reference)
#include <cuda_runtime.h>
#include <cuda_fp16.h>

#define NN 50000
#define EE 800000

// packed f32x2 FMA (PTX-only; ptxas won't auto-fuse)
#define FFMA2(d, a, b) asm("fma.rn.f32x2 %0, %1, %2, %0;" : "+l"(d) : "l"(a), "l"(b))
#define PACK2(d, x, y) asm("mov.b64 %0, {%1, %2};" : "=l"(d) \
                           : "r"(__float_as_uint(x)), "r"(__float_as_uint(y)))
#define UNPK2(x, y, s) do { unsigned int _lo, _hi; \
    asm("mov.b64 {%0, %1}, %2;" : "=r"(_lo), "=r"(_hi) : "l"(s)); \
    (x) = __uint_as_float(_lo); (y) = __uint_as_float(_hi); } while (0)

typedef unsigned long long u64;

// ---------------- scratch ----------------
__device__ unsigned int g_xh[(size_t)NN * 64];  // x_src as half2 (128 cols)
__device__ float  g_a_src[NN * 2];
__device__ float  g_a_dst[NN * 2];
__device__ float4 g_epk [EE];                   // (exp0, exp1, src, dst) by edge id
__device__ int2   g_pk  [EE];                   // CSR payload: (src, half2 att)
__device__ float2 g_sum2[NN];                   // per-dst sum of exp
__device__ uint2  g_aggh[(size_t)NN * 32];      // aggregated messages, half2 x4
__device__ float  g_vedge[128];
__device__ int    g_deg [NN];
__device__ int2   g_row [NN];                   // (beg, deg)
__device__ int    g_cur [NN];
__device__ int    g_total;

// ---------------- kernels ----------------

// x_src = rf @ Wlin (fp16 out) ; a_src = x_src.att_src ; a_dst = lf.udst
// udst computed per block; block 0 also produces g_vedge + zeroes g_total;
// zeroes deg/sum2 for this block's 32 nodes
__global__ void __launch_bounds__(256) k_node(
        const float* __restrict__ rf, const float* __restrict__ lf,
        const float* __restrict__ Wlin, const float* __restrict__ atts,
        const float* __restrict__ attd,
        const float* __restrict__ Wedge, const float* __restrict__ atte) {
    __shared__ float sF[32 * 65];
    __shared__ float sA[128], sU[128];
    int t = threadIdx.x;
    int base = blockIdx.x * 32;
    if (t < 128) {
        sA[t] = atts[t];
        int hh = t >> 6, dd = t & 63;
        float acc = 0.f;
        #pragma unroll 8
        for (int c = 0; c < 64; c++) acc += Wlin[dd * 128 + hh * 64 + c] * attd[hh * 64 + c];
        sU[t] = acc;
    }
    if (blockIdx.x == 0) {
        if (t == 0) g_total = 0;
        if (t >= 128) {                          // t in [128,256): vedge elem t-128
            int idx = t - 128, hh = idx >> 6, dd = idx & 63;
            float acc = 0.f;
            #pragma unroll 8
            for (int c = 0; c < 64; c++) acc += Wedge[dd * 128 + hh * 64 + c] * atte[hh * 64 + c];
            g_vedge[idx] = acc;
        }
    }
    if (t < 32) {
        int nd = base + t;
        if (nd < NN) { g_deg[nd] = 0; g_sum2[nd] = make_float2(0.f, 0.f); }
    }
    for (int i = t; i < 2048; i += 256) {
        int n = i >> 6, k = i & 63, nd = base + n;
        sF[n * 65 + k] = (nd < NN) ? rf[(size_t)nd * 64 + k] : 0.f;
    }
    __syncthreads();
    int cg = t & 31, nl = t >> 5;
    const ulonglong2* W8 = (const ulonglong2*)Wlin;
    u64 A0a = 0, A0b = 0, A1a = 0, A1b = 0, A2a = 0, A2b = 0, A3a = 0, A3b = 0;
    int r0 = (nl * 4 + 0) * 65, r1 = (nl * 4 + 1) * 65,
        r2 = (nl * 4 + 2) * 65, r3 = (nl * 4 + 3) * 65;
    #pragma unroll 8
    for (int k = 0; k < 64; k++) {
        ulonglong2 w = W8[k * 32 + cg];
        float f0 = sF[r0 + k], f1 = sF[r1 + k], f2 = sF[r2 + k], f3 = sF[r3 + k];
        u64 ff;
        PACK2(ff, f0, f0); FFMA2(A0a, ff, w.x); FFMA2(A0b, ff, w.y);
        PACK2(ff, f1, f1); FFMA2(A1a, ff, w.x); FFMA2(A1b, ff, w.y);
        PACK2(ff, f2, f2); FFMA2(A2a, ff, w.x); FFMA2(A2b, ff, w.y);
        PACK2(ff, f3, f3); FFMA2(A3a, ff, w.x); FFMA2(A3b, ff, w.y);
    }
    int h = cg >> 4, c = cg & 15;
    float4 at4 = ((const float4*)sA)[cg];
    float4 u4  = ((const float4*)sU)[h * 16 + c];
    #pragma unroll
    for (int j = 0; j < 4; j++) {
        int nd = base + nl * 4 + j;
        if (nd >= NN) break;
        float ax, ay, az, aw;
        if      (j == 0) { UNPK2(ax, ay, A0a); UNPK2(az, aw, A0b); }
        else if (j == 1) { UNPK2(ax, ay, A1a); UNPK2(az, aw, A1b); }
        else if (j == 2) { UNPK2(ax, ay, A2a); UNPK2(az, aw, A2b); }
        else             { UNPK2(ax, ay, A3a); UNPK2(az, aw, A3b); }
        __half2 h01 = __floats2half2_rn(ax, ay);
        __half2 h23 = __floats2half2_rn(az, aw);
        uint2 st;
        st.x = *reinterpret_cast<unsigned int*>(&h01);
        st.y = *reinterpret_cast<unsigned int*>(&h23);
        ((uint2*)g_xh)[(size_t)nd * 32 + cg] = st;
        float p = ax * at4.x + ay * at4.y + az * at4.z + aw * at4.w;
        float4 l4 = ((const float4*)lf)[(size_t)nd * 16 + c];
        float q = l4.x * u4.x + l4.y * u4.y + l4.z * u4.z + l4.w * u4.w;
        p += __shfl_xor_sync(0xffffffffu, p, 8);
        p += __shfl_xor_sync(0xffffffffu, p, 4);
        p += __shfl_xor_sync(0xffffffffu, p, 2);
        p += __shfl_xor_sync(0xffffffffu, p, 1);
        q += __shfl_xor_sync(0xffffffffu, q, 8);
        q += __shfl_xor_sync(0xffffffffu, q, 4);
        q += __shfl_xor_sync(0xffffffffu, q, 2);
        q += __shfl_xor_sync(0xffffffffu, q, 1);
        if (cg == 0)  { g_a_src[nd * 2 + 0] = p; g_a_dst[nd * 2 + 0] = q; }
        if (cg == 16) { g_a_src[nd * 2 + 1] = p; g_a_dst[nd * 2 + 1] = q; }
    }
}

// 2 lanes per edge (MLP=8): alpha -> leaky -> exp ; fat record (e0,e1,src,dst)
__global__ void __launch_bounds__(256) k_edge_alpha(
        const float* __restrict__ ef, const int* __restrict__ ei) {
    __shared__ float sv[128];
    int t = threadIdx.x;
    int e = blockIdx.x * 128 + (t >> 1);
    int g = t & 1;
    int src = 0, dst = 0;
    if (g == 0) { src = __ldg(&ei[e]); dst = __ldg(&ei[EE + e]); }
    if (t < 128) sv[t] = g_vedge[t];
    const float4* E4 = (const float4*)ef;
    float4 v[8];
    #pragma unroll
    for (int j = 0; j < 8; j++) v[j] = __ldcs(&E4[(size_t)e * 16 + g * 8 + j]);
    __syncthreads();
    float2 as = make_float2(0.f, 0.f), ad = as;
    if (g == 0) {
        as = ((const float2*)g_a_src)[src];
        ad = ((const float2*)g_a_dst)[dst];
    }
    const float4* S4 = (const float4*)sv;
    float p0 = 0.f, p1 = 0.f;
    #pragma unroll
    for (int j = 0; j < 8; j++) {
        float4 s0 = S4[g * 8 + j];
        float4 s1 = S4[16 + g * 8 + j];
        p0 += v[j].x * s0.x + v[j].y * s0.y + v[j].z * s0.z + v[j].w * s0.w;
        p1 += v[j].x * s1.x + v[j].y * s1.y + v[j].z * s1.z + v[j].w * s1.w;
    }
    p0 += __shfl_xor_sync(0xffffffffu, p0, 1);
    p1 += __shfl_xor_sync(0xffffffffu, p1, 1);
    if (g == 0) {
        float a0 = as.x + ad.x + p0;
        float a1 = as.y + ad.y + p1;
        a0 = a0 > 0.f ? a0 : 0.2f * a0;
        a1 = a1 > 0.f ? a1 : 0.2f * a1;
        float e0 = __expf(a0), e1 = __expf(a1);
        g_epk[e] = make_float4(e0, e1, __int_as_float(src), __int_as_float(dst));
        atomicAdd(&g_deg[dst], 1);
        atomicAdd(&g_sum2[dst].x, e0);
        atomicAdd(&g_sum2[dst].y, e1);
    }
}

// CSR range allocation: block scan + one global atomic
__global__ void k_alloc() {
    __shared__ int wsum[8];
    __shared__ int sbase;
    int t = threadIdx.x;
    int i = blockIdx.x * 256 + t;
    int d = (i < NN) ? g_deg[i] : 0;
    int lane = t & 31, w = t >> 5;
    int x = d;
    #pragma unroll
    for (int o = 1; o < 32; o <<= 1) {
        int v = __shfl_up_sync(0xffffffffu, x, o);
        if (lane >= o) x += v;
    }
    if (lane == 31) wsum[w] = x;
    __syncthreads();
    if (t == 0) {
        int run = 0;
        #pragma unroll
        for (int j = 0; j < 8; j++) { int v = wsum[j]; wsum[j] = run; run += v; }
        sbase = atomicAdd(&g_total, run);
    }
    __syncthreads();
    int excl = sbase + wsum[w] + x - d;
    if (i < NN) { g_row[i] = make_int2(excl, d); g_cur[i] = excl; }
}

// CSR fill: one fat-record load; 8B packed scatter; edge_index + att coalesced
__global__ void k_fill(float* __restrict__ out, int hasEi, int hasAtt) {
    int e = blockIdx.x * blockDim.x + threadIdx.x;
    if (e >= EE) return;
    float4 rec = g_epk[e];
    int src = __float_as_int(rec.z), dst = __float_as_int(rec.w);
    float2 sm = g_sum2[dst];
    float2 att = make_float2(rec.x / (sm.x + 1e-16f), rec.y / (sm.y + 1e-16f));
    int pos = atomicAdd(&g_cur[dst], 1);
    __half2 ah = __floats2half2_rn(att.x, att.y);
    int2 pk;
    pk.x = src;
    pk.y = *reinterpret_cast<int*>(&ah);
    g_pk[pos] = pk;
    if (hasAtt)
        ((float2*)(out + (size_t)NN * 64 + 2 * EE))[e] = att;
    if (hasEi) {
        out[NN * 64 + e]      = (float)src;
        out[NN * 64 + EE + e] = (float)dst;
    }
}

// warp per dst: gather-accumulate, payload loads double-buffered
__global__ void __launch_bounds__(256) k_gat() {
    int dst  = (blockIdx.x * blockDim.x + threadIdx.x) >> 5;
    int lane = threadIdx.x & 31;
    if (dst >= NN) return;
    int2 row = g_row[dst];
    int beg = row.x, end = row.x + row.y;
    int h = lane >> 4;
    float4 acc = make_float4(0.f, 0.f, 0.f, 0.f);
    const uint2* X = (const uint2*)g_xh;
    const int2* P = g_pk;
    int i = beg;
    int2 pA, pB, pC, pD;
    if (i + 4 <= end) { pA = P[i]; pB = P[i + 1]; pC = P[i + 2]; pD = P[i + 3]; }
    while (i + 4 <= end) {
        int ni = i + 4;
        int2 qA, qB, qC, qD;
        if (ni + 4 <= end) { qA = P[ni]; qB = P[ni + 1]; qC = P[ni + 2]; qD = P[ni + 3]; }
        uint2 uA = X[(size_t)pA.x * 32 + lane];
        uint2 uB = X[(size_t)pB.x * 32 + lane];
        uint2 uC = X[(size_t)pC.x * 32 + lane];
        uint2 uD = X[(size_t)pD.x * 32 + lane];
        float2 tA = __half22float2(*reinterpret_cast<__half2*>(&pA.y));
        float2 tB = __half22float2(*reinterpret_cast<__half2*>(&pB.y));
        float2 tC = __half22float2(*reinterpret_cast<__half2*>(&pC.y));
        float2 tD = __half22float2(*reinterpret_cast<__half2*>(&pD.y));
        float aA = h ? tA.y : tA.x;
        float aB = h ? tB.y : tB.x;
        float aC = h ? tC.y : tC.x;
        float aD = h ? tD.y : tD.x;
        float2 x0, x1;
        x0 = __half22float2(*reinterpret_cast<__half2*>(&uA.x));
        x1 = __half22float2(*reinterpret_cast<__half2*>(&uA.y));
        acc.x += aA * x0.x; acc.y += aA * x0.y; acc.z += aA * x1.x; acc.w += aA * x1.y;
        x0 = __half22float2(*reinterpret_cast<__half2*>(&uB.x));
        x1 = __half22float2(*reinterpret_cast<__half2*>(&uB.y));
        acc.x += aB * x0.x; acc.y += aB * x0.y; acc.z += aB * x1.x; acc.w += aB * x1.y;
        x0 = __half22float2(*reinterpret_cast<__half2*>(&uC.x));
        x1 = __half22float2(*reinterpret_cast<__half2*>(&uC.y));
        acc.x += aC * x0.x; acc.y += aC * x0.y; acc.z += aC * x1.x; acc.w += aC * x1.y;
        x0 = __half22float2(*reinterpret_cast<__half2*>(&uD.x));
        x1 = __half22float2(*reinterpret_cast<__half2*>(&uD.y));
        acc.x += aD * x0.x; acc.y += aD * x0.y; acc.z += aD * x1.x; acc.w += aD * x1.y;
        pA = qA; pB = qB; pC = qC; pD = qD;
        i = ni;
    }
    for (; i < end; i++) {
        int2 pE = P[i];
        float2 tE = __half22float2(*reinterpret_cast<__half2*>(&pE.y));
        float aE = h ? tE.y : tE.x;
        uint2 uE = X[(size_t)pE.x * 32 + lane];
        float2 x0 = __half22float2(*reinterpret_cast<__half2*>(&uE.x));
        float2 x1 = __half22float2(*reinterpret_cast<__half2*>(&uE.y));
        acc.x += aE * x0.x; acc.y += aE * x0.y; acc.z += aE * x1.x; acc.w += aE * x1.y;
    }
    __half2 a01 = __floats2half2_rn(acc.x, acc.y);
    __half2 a23 = __floats2half2_rn(acc.z, acc.w);
    uint2 st;
    st.x = *reinterpret_cast<unsigned int*>(&a01);
    st.y = *reinterpret_cast<unsigned int*>(&a23);
    g_aggh[(size_t)dst * 32 + lane] = st;
}

// fused dense chain; 128 thr, 32 nodes per block, FFMA2, sU aliased into sF
__global__ void __launch_bounds__(128) k_dense(
        const float* __restrict__ lf,
        const float* __restrict__ Wlt, const float* __restrict__ blt,
        const float* __restrict__ bconv,
        const float* __restrict__ Wfm, const float* __restrict__ bfm,
        const float* __restrict__ Wpc, const float* __restrict__ bpc,
        float* __restrict__ out) {
    __shared__ float sF[32 * 132];
    __shared__ float sT[32 * 68];
    __shared__ float sL[32 * 68];
    __shared__ float sbc[128];
    float* sU = sF;                       // reuse: sF dead after stage 1
    int t = threadIdx.x;
    if (t < 128) sbc[t] = bconv[t];
    int base = blockIdx.x * 32;
    __syncthreads();
    for (int i = t; i < 2048; i += 128) {
        int n = i >> 6, c2 = i & 63;
        int nd = base + n;
        float2 f = make_float2(0.f, 0.f);
        if (nd < NN) {
            unsigned int u = ((const unsigned int*)g_aggh)[(size_t)nd * 64 + c2];
            f = __half22float2(*reinterpret_cast<__half2*>(&u));
        }
        float v0 = f.x + sbc[c2 * 2], v1 = f.y + sbc[c2 * 2 + 1];
        v0 = v0 > 0.f ? v0 : 0.f;
        v1 = v1 > 0.f ? v1 : 0.f;
        *(float2*)&sF[n * 132 + c2 * 2] = make_float2(v0, v1);
    }
    for (int i = t; i < 2048; i += 128) {
        int n = i >> 6, k = i & 63, nd = base + n;
        sL[n * 68 + k] = (nd < NN) ? lf[(size_t)nd * 64 + k] : 0.f;
    }
    __syncthreads();
    int cg = t & 15, nl = t >> 4;
    int n0 = nl * 4, n1 = nl * 4 + 1, n2 = nl * 4 + 2, n3 = nl * 4 + 3;
    // ---- stage 1: K=128, Wlt -> sT ----
    {
        const ulonglong2* W8 = (const ulonglong2*)Wlt;
        u64 A0a = 0, A0b = 0, A1a = 0, A1b = 0, A2a = 0, A2b = 0, A3a = 0, A3b = 0;
        int r0 = n0 * 132, r1 = n1 * 132, r2 = n2 * 132, r3 = n3 * 132;
        #pragma unroll 8
        for (int k = 0; k < 128; k++) {
            ulonglong2 w = W8[k * 16 + cg];
            float f0 = sF[r0 + k], f1 = sF[r1 + k], f2 = sF[r2 + k], f3 = sF[r3 + k];
            u64 ff;
            PACK2(ff, f0, f0); FFMA2(A0a, ff, w.x); FFMA2(A0b, ff, w.y);
            PACK2(ff, f1, f1); FFMA2(A1a, ff, w.x); FFMA2(A1b, ff, w.y);
            PACK2(ff, f2, f2); FFMA2(A2a, ff, w.x); FFMA2(A2b, ff, w.y);
            PACK2(ff, f3, f3); FFMA2(A3a, ff, w.x); FFMA2(A3b, ff, w.y);
        }
        float4 b4 = ((const float4*)blt)[cg];
        __syncthreads();
        #pragma unroll
        for (int j = 0; j < 4; j++) {
            float ax, ay, az, aw;
            if      (j == 0) { UNPK2(ax, ay, A0a); UNPK2(az, aw, A0b); }
            else if (j == 1) { UNPK2(ax, ay, A1a); UNPK2(az, aw, A1b); }
            else if (j == 2) { UNPK2(ax, ay, A2a); UNPK2(az, aw, A2b); }
            else             { UNPK2(ax, ay, A3a); UNPK2(az, aw, A3b); }
            float4 o;
            o.x = ax + b4.x; o.y = ay + b4.y; o.z = az + b4.z; o.w = aw + b4.w;
            o.x = o.x > 0.f ? o.x : 0.f;
            o.y = o.y > 0.f ? o.y : 0.f;
            o.z = o.z > 0.f ? o.z : 0.f;
            o.w = o.w > 0.f ? o.w : 0.f;
            *(float4*)&sT[(nl * 4 + j) * 68 + cg * 4] = o;
        }
    }
    __syncthreads();
    // ---- stage 2: K=64, Wfm -> sU (aliased into sF) ----
    {
        const ulonglong2* W8 = (const ulonglong2*)Wfm;
        u64 A0a = 0, A0b = 0, A1a = 0, A1b = 0, A2a = 0, A2b = 0, A3a = 0, A3b = 0;
        int r0 = n0 * 68, r1 = n1 * 68, r2 = n2 * 68, r3 = n3 * 68;
        #pragma unroll 8
        for (int k = 0; k < 64; k++) {
            ulonglong2 w = W8[k * 16 + cg];
            float f0 = sT[r0 + k], f1 = sT[r1 + k], f2 = sT[r2 + k], f3 = sT[r3 + k];
            u64 ff;
            PACK2(ff, f0, f0); FFMA2(A0a, ff, w.x); FFMA2(A0b, ff, w.y);
            PACK2(ff, f1, f1); FFMA2(A1a, ff, w.x); FFMA2(A1b, ff, w.y);
            PACK2(ff, f2, f2); FFMA2(A2a, ff, w.x); FFMA2(A2b, ff, w.y);
            PACK2(ff, f3, f3); FFMA2(A3a, ff, w.x); FFMA2(A3b, ff, w.y);
        }
        float4 b4 = ((const float4*)bfm)[cg];
        #pragma unroll
        for (int j = 0; j < 4; j++) {
            float ax, ay, az, aw;
            if      (j == 0) { UNPK2(ax, ay, A0a); UNPK2(az, aw, A0b); }
            else if (j == 1) { UNPK2(ax, ay, A1a); UNPK2(az, aw, A1b); }
            else if (j == 2) { UNPK2(ax, ay, A2a); UNPK2(az, aw, A2b); }
            else             { UNPK2(ax, ay, A3a); UNPK2(az, aw, A3b); }
            float4 o;
            o.x = ax + b4.x; o.y = ay + b4.y; o.z = az + b4.z; o.w = aw + b4.w;
            *(float4*)&sU[(nl * 4 + j) * 68 + cg * 4] = o;
        }
    }
    __syncthreads();
    // ---- stage 3: out = sL @ Wpc[0:64] + sU @ Wpc[64:128] + bpc ----
    {
        const ulonglong2* W8 = (const ulonglong2*)Wpc;
        u64 A0a = 0, A0b = 0, A1a = 0, A1b = 0, A2a = 0, A2b = 0, A3a = 0, A3b = 0;
        int r0 = n0 * 68, r1 = n1 * 68, r2 = n2 * 68, r3 = n3 * 68;
        #pragma unroll 8
        for (int k = 0; k < 64; k++) {
            ulonglong2 w = W8[k * 16 + cg];
            float f0 = sL[r0 + k], f1 = sL[r1 + k], f2 = sL[r2 + k], f3 = sL[r3 + k];
            u64 ff;
            PACK2(ff, f0, f0); FFMA2(A0a, ff, w.x); FFMA2(A0b, ff, w.y);
            PACK2(ff, f1, f1); FFMA2(A1a, ff, w.x); FFMA2(A1b, ff, w.y);
            PACK2(ff, f2, f2); FFMA2(A2a, ff, w.x); FFMA2(A2b, ff, w.y);
            PACK2(ff, f3, f3); FFMA2(A3a, ff, w.x); FFMA2(A3b, ff, w.y);
        }
        #pragma unroll 8
        for (int k = 0; k < 64; k++) {
            ulonglong2 w = W8[(64 + k) * 16 + cg];
            float f0 = sU[r0 + k], f1 = sU[r1 + k], f2 = sU[r2 + k], f3 = sU[r3 + k];
            u64 ff;
            PACK2(ff, f0, f0); FFMA2(A0a, ff, w.x); FFMA2(A0b, ff, w.y);
            PACK2(ff, f1, f1); FFMA2(A1a, ff, w.x); FFMA2(A1b, ff, w.y);
            PACK2(ff, f2, f2); FFMA2(A2a, ff, w.x); FFMA2(A2b, ff, w.y);
            PACK2(ff, f3, f3); FFMA2(A3a, ff, w.x); FFMA2(A3b, ff, w.y);
        }
        float4 b4 = ((const float4*)bpc)[cg];
        #pragma unroll
        for (int j = 0; j < 4; j++) {
            int nd = base + nl * 4 + j;
            if (nd >= NN) break;
            float ax, ay, az, aw;
            if      (j == 0) { UNPK2(ax, ay, A0a); UNPK2(az, aw, A0b); }
            else if (j == 1) { UNPK2(ax, ay, A1a); UNPK2(az, aw, A1b); }
            else if (j == 2) { UNPK2(ax, ay, A2a); UNPK2(az, aw, A2b); }
            else             { UNPK2(ax, ay, A3a); UNPK2(az, aw, A3b); }
            float4 o;
            o.x = ax + b4.x; o.y = ay + b4.y; o.z = az + b4.z; o.w = aw + b4.w;
            ((float4*)out)[(size_t)nd * 16 + cg] = o;
        }
    }
}

// ---------------- launch ----------------
extern "C" void kernel_launch(void* const* d_in, const int* in_sizes, int n_in,
                              void* d_out, int out_size) {
    int k = (n_in >= 17) ? 5 : 4;
    const float* lf    = (const float*)d_in[0];
    const int*   ei    = (const int*)  d_in[1];
    const float* ef    = (const float*)d_in[2];
    const float* rf    = (const float*)d_in[3];
    const float* Wlin  = (const float*)d_in[k + 0];
    const float* atts  = (const float*)d_in[k + 1];
    const float* attd  = (const float*)d_in[k + 2];
    const float* Wedge = (const float*)d_in[k + 3];
    const float* atte  = (const float*)d_in[k + 4];
    const float* bconv = (const float*)d_in[k + 5];
    const float* Wlt   = (const float*)d_in[k + 6];
    const float* blt   = (const float*)d_in[k + 7];
    const float* Wfm   = (const float*)d_in[k + 8];
    const float* bfm   = (const float*)d_in[k + 9];
    const float* Wpc   = (const float*)d_in[k + 10];
    const float* bpc   = (const float*)d_in[k + 11];
    float* out = (float*)d_out;

    int hasEi  = out_size >= NN * 64 + 2 * EE;
    int hasAtt = out_size >= NN * 64 + 2 * EE + 2 * EE;

    int nblk = (NN + 31) / 32;  // 1563
    k_node<<<nblk, 256>>>(rf, lf, Wlin, atts, attd, Wedge, atte);
    k_edge_alpha<<<EE / 128, 256>>>(ef, ei);
    k_alloc<<<(NN + 255) / 256, 256>>>();
    k_fill<<<(EE + 255) / 256, 256>>>(out, hasEi, hasAtt);
    k_gat<<<(NN + 7) / 8, 256>>>();
    k_dense<<<nblk, 128>>>(lf, Wlt, blt, bconv, Wfm, bfm, Wpc, bpc, out);
}

// round 14
// speedup vs baseline: 1.2242x; 1.2242x over previous
#include <cuda_runtime.h>
#include <cuda_fp16.h>

#define NN 50000
#define EE 800000

// packed f32x2 FMA (PTX-only; ptxas won't auto-fuse)
#define FFMA2(d, a, b) asm("fma.rn.f32x2 %0, %1, %2, %0;" : "+l"(d) : "l"(a), "l"(b))
#define PACK2(d, x, y) asm("mov.b64 %0, {%1, %2};" : "=l"(d) \
                           : "r"(__float_as_uint(x)), "r"(__float_as_uint(y)))
#define UNPK2(x, y, s) do { unsigned int _lo, _hi; \
    asm("mov.b64 {%0, %1}, %2;" : "=r"(_lo), "=r"(_hi) : "l"(s)); \
    (x) = __uint_as_float(_lo); (y) = __uint_as_float(_hi); } while (0)

typedef unsigned long long u64;

// ---------------- scratch ----------------
__device__ unsigned int g_xh[(size_t)NN * 64];  // x_src as half2 (128 cols)
__device__ float  g_a_src[NN * 2];
__device__ float  g_a_dst[NN * 2];
__device__ float4 g_epk [EE];                   // (exp0, exp1, src, dst) by edge id
__device__ int2   g_pk  [EE];                   // CSR payload: (src, half2 att)
__device__ float2 g_sum2[NN];                   // per-dst sum of exp
__device__ uint2  g_aggh[(size_t)NN * 32];      // aggregated messages, half2 x4
__device__ float  g_vedge[128];
__device__ float  g_udst [128];
__device__ int    g_deg [NN];
__device__ int2   g_row [NN];                   // (beg, deg)
__device__ int    g_cur [NN];
__device__ int    g_total;

// ---------------- kernels ----------------

// single block: fold attention vectors; zero the global cursor
__global__ void k_vec(const float* __restrict__ Wlin, const float* __restrict__ attd,
                      const float* __restrict__ Wedge, const float* __restrict__ atte) {
    int t = threadIdx.x;
    if (t == 0) g_total = 0;
    if (t < 128) {
        int h = t >> 6, d = t & 63;
        float acc = 0.f;
        #pragma unroll 8
        for (int c = 0; c < 64; c++) acc += Wlin[d * 128 + h * 64 + c] * attd[h * 64 + c];
        g_udst[h * 64 + d] = acc;
    } else {
        int idx = t - 128;
        int h = idx >> 6, d = idx & 63;
        float acc = 0.f;
        #pragma unroll 8
        for (int c = 0; c < 64; c++) acc += Wedge[d * 128 + h * 64 + c] * atte[h * 64 + c];
        g_vedge[h * 64 + d] = acc;
    }
}

// x_src = rf @ Wlin (fp16 out) ; a_src = x_src.att_src ; a_dst = lf.udst
// also zeroes deg/sum2 for this block's 32 nodes
__global__ void __launch_bounds__(256) k_node(
        const float* __restrict__ rf, const float* __restrict__ lf,
        const float* __restrict__ Wlin, const float* __restrict__ atts) {
    __shared__ float sF[32 * 65];
    __shared__ float sA[128], sU[128];
    int t = threadIdx.x;
    if (t < 128) { sA[t] = atts[t]; sU[t] = g_udst[t]; }
    int cg = t & 31, nl = t >> 5;
    int base = blockIdx.x * 32;
    if (t < 32) {
        int nd = base + t;
        if (nd < NN) { g_deg[nd] = 0; g_sum2[nd] = make_float2(0.f, 0.f); }
    }
    for (int i = t; i < 2048; i += 256) {
        int n = i >> 6, k = i & 63, nd = base + n;
        sF[n * 65 + k] = (nd < NN) ? rf[(size_t)nd * 64 + k] : 0.f;
    }
    __syncthreads();
    const ulonglong2* W8 = (const ulonglong2*)Wlin;
    u64 A0a = 0, A0b = 0, A1a = 0, A1b = 0, A2a = 0, A2b = 0, A3a = 0, A3b = 0;
    int r0 = (nl * 4 + 0) * 65, r1 = (nl * 4 + 1) * 65,
        r2 = (nl * 4 + 2) * 65, r3 = (nl * 4 + 3) * 65;
    #pragma unroll 8
    for (int k = 0; k < 64; k++) {
        ulonglong2 w = W8[k * 32 + cg];
        float f0 = sF[r0 + k], f1 = sF[r1 + k], f2 = sF[r2 + k], f3 = sF[r3 + k];
        u64 ff;
        PACK2(ff, f0, f0); FFMA2(A0a, ff, w.x); FFMA2(A0b, ff, w.y);
        PACK2(ff, f1, f1); FFMA2(A1a, ff, w.x); FFMA2(A1b, ff, w.y);
        PACK2(ff, f2, f2); FFMA2(A2a, ff, w.x); FFMA2(A2b, ff, w.y);
        PACK2(ff, f3, f3); FFMA2(A3a, ff, w.x); FFMA2(A3b, ff, w.y);
    }
    int h = cg >> 4, c = cg & 15;
    float4 at4 = ((const float4*)sA)[cg];
    float4 u4  = ((const float4*)sU)[h * 16 + c];
    #pragma unroll
    for (int j = 0; j < 4; j++) {
        int nd = base + nl * 4 + j;
        if (nd >= NN) break;
        float ax, ay, az, aw;
        if      (j == 0) { UNPK2(ax, ay, A0a); UNPK2(az, aw, A0b); }
        else if (j == 1) { UNPK2(ax, ay, A1a); UNPK2(az, aw, A1b); }
        else if (j == 2) { UNPK2(ax, ay, A2a); UNPK2(az, aw, A2b); }
        else             { UNPK2(ax, ay, A3a); UNPK2(az, aw, A3b); }
        __half2 h01 = __floats2half2_rn(ax, ay);
        __half2 h23 = __floats2half2_rn(az, aw);
        uint2 st;
        st.x = *reinterpret_cast<unsigned int*>(&h01);
        st.y = *reinterpret_cast<unsigned int*>(&h23);
        ((uint2*)g_xh)[(size_t)nd * 32 + cg] = st;
        float p = ax * at4.x + ay * at4.y + az * at4.z + aw * at4.w;
        float4 l4 = ((const float4*)lf)[(size_t)nd * 16 + c];
        float q = l4.x * u4.x + l4.y * u4.y + l4.z * u4.z + l4.w * u4.w;
        p += __shfl_xor_sync(0xffffffffu, p, 8);
        p += __shfl_xor_sync(0xffffffffu, p, 4);
        p += __shfl_xor_sync(0xffffffffu, p, 2);
        p += __shfl_xor_sync(0xffffffffu, p, 1);
        q += __shfl_xor_sync(0xffffffffu, q, 8);
        q += __shfl_xor_sync(0xffffffffu, q, 4);
        q += __shfl_xor_sync(0xffffffffu, q, 2);
        q += __shfl_xor_sync(0xffffffffu, q, 1);
        if (cg == 0)  { g_a_src[nd * 2 + 0] = p; g_a_dst[nd * 2 + 0] = q; }
        if (cg == 16) { g_a_src[nd * 2 + 1] = p; g_a_dst[nd * 2 + 1] = q; }
    }
}

// 4 lanes per edge: alpha -> leaky -> exp ; writes fat record (e0,e1,src,dst)
__global__ void __launch_bounds__(256) k_edge_alpha(
        const float* __restrict__ ef, const int* __restrict__ ei) {
    __shared__ float sv[128];
    int t = threadIdx.x;
    int e = blockIdx.x * 64 + (t >> 2);
    int g = t & 3;
    int src = 0, dst = 0;
    if (g == 0) { src = __ldg(&ei[e]); dst = __ldg(&ei[EE + e]); }
    if (t < 128) sv[t] = g_vedge[t];
    const float4* E4 = (const float4*)ef;
    float4 v0 = __ldcs(&E4[(size_t)e * 16 + g]);
    float4 v1 = __ldcs(&E4[(size_t)e * 16 + g + 4]);
    float4 v2 = __ldcs(&E4[(size_t)e * 16 + g + 8]);
    float4 v3 = __ldcs(&E4[(size_t)e * 16 + g + 12]);
    __syncthreads();
    float2 as = make_float2(0.f, 0.f), ad = as;
    if (g == 0) {
        as = ((const float2*)g_a_src)[src];
        ad = ((const float2*)g_a_dst)[dst];
    }
    const float4* S4 = (const float4*)sv;
    float4 s0, s1;
    float p0 = 0.f, p1 = 0.f;
    s0 = S4[g];      s1 = S4[16 + g];
    p0 += v0.x*s0.x + v0.y*s0.y + v0.z*s0.z + v0.w*s0.w;
    p1 += v0.x*s1.x + v0.y*s1.y + v0.z*s1.z + v0.w*s1.w;
    s0 = S4[g + 4];  s1 = S4[20 + g];
    p0 += v1.x*s0.x + v1.y*s0.y + v1.z*s0.z + v1.w*s0.w;
    p1 += v1.x*s1.x + v1.y*s1.y + v1.z*s1.z + v1.w*s1.w;
    s0 = S4[g + 8];  s1 = S4[24 + g];
    p0 += v2.x*s0.x + v2.y*s0.y + v2.z*s0.z + v2.w*s0.w;
    p1 += v2.x*s1.x + v2.y*s1.y + v2.z*s1.z + v2.w*s1.w;
    s0 = S4[g + 12]; s1 = S4[28 + g];
    p0 += v3.x*s0.x + v3.y*s0.y + v3.z*s0.z + v3.w*s0.w;
    p1 += v3.x*s1.x + v3.y*s1.y + v3.z*s1.z + v3.w*s1.w;
    float a = __shfl_xor_sync(0xffffffffu, p0, 2);
    float b = __shfl_xor_sync(0xffffffffu, p1, 2);
    float r = (g & 2) ? (p1 + b) : (p0 + a);
    r += __shfl_xor_sync(0xffffffffu, r, 1);
    float other = __shfl_xor_sync(0xffffffffu, r, 2);
    if (g == 0) {
        float a0 = as.x + ad.x + r;
        float a1 = as.y + ad.y + other;
        a0 = a0 > 0.f ? a0 : 0.2f * a0;
        a1 = a1 > 0.f ? a1 : 0.2f * a1;
        float e0 = __expf(a0), e1 = __expf(a1);
        g_epk[e] = make_float4(e0, e1, __int_as_float(src), __int_as_float(dst));
        atomicAdd(&g_deg[dst], 1);
        atomicAdd(&g_sum2[dst].x, e0);
        atomicAdd(&g_sum2[dst].y, e1);
    }
}

// CSR range allocation: block scan + one global atomic
__global__ void k_alloc() {
    __shared__ int wsum[8];
    __shared__ int sbase;
    int t = threadIdx.x;
    int i = blockIdx.x * 256 + t;
    int d = (i < NN) ? g_deg[i] : 0;
    int lane = t & 31, w = t >> 5;
    int x = d;
    #pragma unroll
    for (int o = 1; o < 32; o <<= 1) {
        int v = __shfl_up_sync(0xffffffffu, x, o);
        if (lane >= o) x += v;
    }
    if (lane == 31) wsum[w] = x;
    __syncthreads();
    if (t == 0) {
        int run = 0;
        #pragma unroll
        for (int j = 0; j < 8; j++) { int v = wsum[j]; wsum[j] = run; run += v; }
        sbase = atomicAdd(&g_total, run);
    }
    __syncthreads();
    int excl = sbase + wsum[w] + x - d;
    if (i < NN) { g_row[i] = make_int2(excl, d); g_cur[i] = excl; }
}

// CSR fill: 2 edges per thread (independent chains, MLP x2)
__global__ void k_fill(float* __restrict__ out, int hasEi, int hasAtt) {
    int base = (blockIdx.x * blockDim.x + threadIdx.x) * 2;
    if (base >= EE) return;
    float4 recA = g_epk[base];
    float4 recB = g_epk[base + 1];            // EE even: base+1 < EE always
    int srcA = __float_as_int(recA.z), dstA = __float_as_int(recA.w);
    int srcB = __float_as_int(recB.z), dstB = __float_as_int(recB.w);
    float2 smA = g_sum2[dstA];
    float2 smB = g_sum2[dstB];
    float2 attA = make_float2(recA.x / (smA.x + 1e-16f), recA.y / (smA.y + 1e-16f));
    float2 attB = make_float2(recB.x / (smB.x + 1e-16f), recB.y / (smB.y + 1e-16f));
    int posA = atomicAdd(&g_cur[dstA], 1);
    int posB = atomicAdd(&g_cur[dstB], 1);
    __half2 ahA = __floats2half2_rn(attA.x, attA.y);
    __half2 ahB = __floats2half2_rn(attB.x, attB.y);
    int2 pkA, pkB;
    pkA.x = srcA; pkA.y = *reinterpret_cast<int*>(&ahA);
    pkB.x = srcB; pkB.y = *reinterpret_cast<int*>(&ahB);
    g_pk[posA] = pkA;
    g_pk[posB] = pkB;
    if (hasAtt) {
        float4 av = make_float4(attA.x, attA.y, attB.x, attB.y);
        ((float4*)(out + (size_t)NN * 64 + 2 * EE))[base >> 1] = av;
    }
    if (hasEi) {
        ((float2*)(out + NN * 64))[base >> 1]      = make_float2((float)srcA, (float)srcB);
        ((float2*)(out + NN * 64 + EE))[base >> 1] = make_float2((float)dstA, (float)dstB);
    }
}

// warp per dst: gather-accumulate (fp16 x_src, fp16 att), fp16 agg out
__global__ void __launch_bounds__(256) k_gat() {
    int dst  = (blockIdx.x * blockDim.x + threadIdx.x) >> 5;
    int lane = threadIdx.x & 31;
    if (dst >= NN) return;
    int2 row = g_row[dst];
    int beg = row.x, end = row.x + row.y;
    int h = lane >> 4;
    float4 acc = make_float4(0.f, 0.f, 0.f, 0.f);
    const uint2* X = (const uint2*)g_xh;
    const int2* P = g_pk;
    int i = beg;
    for (; i + 4 <= end; i += 4) {
        int2 pA = P[i], pB = P[i + 1], pC = P[i + 2], pD = P[i + 3];
        uint2 uA = X[(size_t)pA.x * 32 + lane];
        uint2 uB = X[(size_t)pB.x * 32 + lane];
        uint2 uC = X[(size_t)pC.x * 32 + lane];
        uint2 uD = X[(size_t)pD.x * 32 + lane];
        float2 tA = __half22float2(*reinterpret_cast<__half2*>(&pA.y));
        float2 tB = __half22float2(*reinterpret_cast<__half2*>(&pB.y));
        float2 tC = __half22float2(*reinterpret_cast<__half2*>(&pC.y));
        float2 tD = __half22float2(*reinterpret_cast<__half2*>(&pD.y));
        float aA = h ? tA.y : tA.x;
        float aB = h ? tB.y : tB.x;
        float aC = h ? tC.y : tC.x;
        float aD = h ? tD.y : tD.x;
        float2 x0, x1;
        x0 = __half22float2(*reinterpret_cast<__half2*>(&uA.x));
        x1 = __half22float2(*reinterpret_cast<__half2*>(&uA.y));
        acc.x += aA * x0.x; acc.y += aA * x0.y; acc.z += aA * x1.x; acc.w += aA * x1.y;
        x0 = __half22float2(*reinterpret_cast<__half2*>(&uB.x));
        x1 = __half22float2(*reinterpret_cast<__half2*>(&uB.y));
        acc.x += aB * x0.x; acc.y += aB * x0.y; acc.z += aB * x1.x; acc.w += aB * x1.y;
        x0 = __half22float2(*reinterpret_cast<__half2*>(&uC.x));
        x1 = __half22float2(*reinterpret_cast<__half2*>(&uC.y));
        acc.x += aC * x0.x; acc.y += aC * x0.y; acc.z += aC * x1.x; acc.w += aC * x1.y;
        x0 = __half22float2(*reinterpret_cast<__half2*>(&uD.x));
        x1 = __half22float2(*reinterpret_cast<__half2*>(&uD.y));
        acc.x += aD * x0.x; acc.y += aD * x0.y; acc.z += aD * x1.x; acc.w += aD * x1.y;
    }
    for (; i < end; i++) {
        int2 pA = P[i];
        float2 tA = __half22float2(*reinterpret_cast<__half2*>(&pA.y));
        float aA = h ? tA.y : tA.x;
        uint2 uA = X[(size_t)pA.x * 32 + lane];
        float2 x0 = __half22float2(*reinterpret_cast<__half2*>(&uA.x));
        float2 x1 = __half22float2(*reinterpret_cast<__half2*>(&uA.y));
        acc.x += aA * x0.x; acc.y += aA * x0.y; acc.z += aA * x1.x; acc.w += aA * x1.y;
    }
    __half2 a01 = __floats2half2_rn(acc.x, acc.y);
    __half2 a23 = __floats2half2_rn(acc.z, acc.w);
    uint2 st;
    st.x = *reinterpret_cast<unsigned int*>(&a01);
    st.y = *reinterpret_cast<unsigned int*>(&a23);
    g_aggh[(size_t)dst * 32 + lane] = st;
}

// fused dense chain; 128 thr, 32 nodes per block, FFMA2, sU aliased into sF
__global__ void __launch_bounds__(128) k_dense(
        const float* __restrict__ lf,
        const float* __restrict__ Wlt, const float* __restrict__ blt,
        const float* __restrict__ bconv,
        const float* __restrict__ Wfm, const float* __restrict__ bfm,
        const float* __restrict__ Wpc, const float* __restrict__ bpc,
        float* __restrict__ out) {
    __shared__ float sF[32 * 132];
    __shared__ float sT[32 * 68];
    __shared__ float sL[32 * 68];
    __shared__ float sbc[128];
    float* sU = sF;                       // reuse: sF dead after stage 1
    int t = threadIdx.x;
    if (t < 128) sbc[t] = bconv[t];
    int base = blockIdx.x * 32;
    __syncthreads();
    for (int i = t; i < 2048; i += 128) {
        int n = i >> 6, c2 = i & 63;
        int nd = base + n;
        float2 f = make_float2(0.f, 0.f);
        if (nd < NN) {
            unsigned int u = ((const unsigned int*)g_aggh)[(size_t)nd * 64 + c2];
            f = __half22float2(*reinterpret_cast<__half2*>(&u));
        }
        float v0 = f.x + sbc[c2 * 2], v1 = f.y + sbc[c2 * 2 + 1];
        v0 = v0 > 0.f ? v0 : 0.f;
        v1 = v1 > 0.f ? v1 : 0.f;
        *(float2*)&sF[n * 132 + c2 * 2] = make_float2(v0, v1);
    }
    for (int i = t; i < 2048; i += 128) {
        int n = i >> 6, k = i & 63, nd = base + n;
        sL[n * 68 + k] = (nd < NN) ? lf[(size_t)nd * 64 + k] : 0.f;
    }
    __syncthreads();
    int cg = t & 15, nl = t >> 4;
    int n0 = nl * 4, n1 = nl * 4 + 1, n2 = nl * 4 + 2, n3 = nl * 4 + 3;
    // ---- stage 1: K=128, Wlt -> sT ----
    {
        const ulonglong2* W8 = (const ulonglong2*)Wlt;
        u64 A0a = 0, A0b = 0, A1a = 0, A1b = 0, A2a = 0, A2b = 0, A3a = 0, A3b = 0;
        int r0 = n0 * 132, r1 = n1 * 132, r2 = n2 * 132, r3 = n3 * 132;
        #pragma unroll 8
        for (int k = 0; k < 128; k++) {
            ulonglong2 w = W8[k * 16 + cg];
            float f0 = sF[r0 + k], f1 = sF[r1 + k], f2 = sF[r2 + k], f3 = sF[r3 + k];
            u64 ff;
            PACK2(ff, f0, f0); FFMA2(A0a, ff, w.x); FFMA2(A0b, ff, w.y);
            PACK2(ff, f1, f1); FFMA2(A1a, ff, w.x); FFMA2(A1b, ff, w.y);
            PACK2(ff, f2, f2); FFMA2(A2a, ff, w.x); FFMA2(A2b, ff, w.y);
            PACK2(ff, f3, f3); FFMA2(A3a, ff, w.x); FFMA2(A3b, ff, w.y);
        }
        float4 b4 = ((const float4*)blt)[cg];
        __syncthreads();
        #pragma unroll
        for (int j = 0; j < 4; j++) {
            float ax, ay, az, aw;
            if      (j == 0) { UNPK2(ax, ay, A0a); UNPK2(az, aw, A0b); }
            else if (j == 1) { UNPK2(ax, ay, A1a); UNPK2(az, aw, A1b); }
            else if (j == 2) { UNPK2(ax, ay, A2a); UNPK2(az, aw, A2b); }
            else             { UNPK2(ax, ay, A3a); UNPK2(az, aw, A3b); }
            float4 o;
            o.x = ax + b4.x; o.y = ay + b4.y; o.z = az + b4.z; o.w = aw + b4.w;
            o.x = o.x > 0.f ? o.x : 0.f;
            o.y = o.y > 0.f ? o.y : 0.f;
            o.z = o.z > 0.f ? o.z : 0.f;
            o.w = o.w > 0.f ? o.w : 0.f;
            *(float4*)&sT[(nl * 4 + j) * 68 + cg * 4] = o;
        }
    }
    __syncthreads();
    // ---- stage 2: K=64, Wfm -> sU (aliased into sF) ----
    {
        const ulonglong2* W8 = (const ulonglong2*)Wfm;
        u64 A0a = 0, A0b = 0, A1a = 0, A1b = 0, A2a = 0, A2b = 0, A3a = 0, A3b = 0;
        int r0 = n0 * 68, r1 = n1 * 68, r2 = n2 * 68, r3 = n3 * 68;
        #pragma unroll 8
        for (int k = 0; k < 64; k++) {
            ulonglong2 w = W8[k * 16 + cg];
            float f0 = sT[r0 + k], f1 = sT[r1 + k], f2 = sT[r2 + k], f3 = sT[r3 + k];
            u64 ff;
            PACK2(ff, f0, f0); FFMA2(A0a, ff, w.x); FFMA2(A0b, ff, w.y);
            PACK2(ff, f1, f1); FFMA2(A1a, ff, w.x); FFMA2(A1b, ff, w.y);
            PACK2(ff, f2, f2); FFMA2(A2a, ff, w.x); FFMA2(A2b, ff, w.y);
            PACK2(ff, f3, f3); FFMA2(A3a, ff, w.x); FFMA2(A3b, ff, w.y);
        }
        float4 b4 = ((const float4*)bfm)[cg];
        #pragma unroll
        for (int j = 0; j < 4; j++) {
            float ax, ay, az, aw;
            if      (j == 0) { UNPK2(ax, ay, A0a); UNPK2(az, aw, A0b); }
            else if (j == 1) { UNPK2(ax, ay, A1a); UNPK2(az, aw, A1b); }
            else if (j == 2) { UNPK2(ax, ay, A2a); UNPK2(az, aw, A2b); }
            else             { UNPK2(ax, ay, A3a); UNPK2(az, aw, A3b); }
            float4 o;
            o.x = ax + b4.x; o.y = ay + b4.y; o.z = az + b4.z; o.w = aw + b4.w;
            *(float4*)&sU[(nl * 4 + j) * 68 + cg * 4] = o;
        }
    }
    __syncthreads();
    // ---- stage 3: out = sL @ Wpc[0:64] + sU @ Wpc[64:128] + bpc ----
    {
        const ulonglong2* W8 = (const ulonglong2*)Wpc;
        u64 A0a = 0, A0b = 0, A1a = 0, A1b = 0, A2a = 0, A2b = 0, A3a = 0, A3b = 0;
        int r0 = n0 * 68, r1 = n1 * 68, r2 = n2 * 68, r3 = n3 * 68;
        #pragma unroll 8
        for (int k = 0; k < 64; k++) {
            ulonglong2 w = W8[k * 16 + cg];
            float f0 = sL[r0 + k], f1 = sL[r1 + k], f2 = sL[r2 + k], f3 = sL[r3 + k];
            u64 ff;
            PACK2(ff, f0, f0); FFMA2(A0a, ff, w.x); FFMA2(A0b, ff, w.y);
            PACK2(ff, f1, f1); FFMA2(A1a, ff, w.x); FFMA2(A1b, ff, w.y);
            PACK2(ff, f2, f2); FFMA2(A2a, ff, w.x); FFMA2(A2b, ff, w.y);
            PACK2(ff, f3, f3); FFMA2(A3a, ff, w.x); FFMA2(A3b, ff, w.y);
        }
        #pragma unroll 8
        for (int k = 0; k < 64; k++) {
            ulonglong2 w = W8[(64 + k) * 16 + cg];
            float f0 = sU[r0 + k], f1 = sU[r1 + k], f2 = sU[r2 + k], f3 = sU[r3 + k];
            u64 ff;
            PACK2(ff, f0, f0); FFMA2(A0a, ff, w.x); FFMA2(A0b, ff, w.y);
            PACK2(ff, f1, f1); FFMA2(A1a, ff, w.x); FFMA2(A1b, ff, w.y);
            PACK2(ff, f2, f2); FFMA2(A2a, ff, w.x); FFMA2(A2b, ff, w.y);
            PACK2(ff, f3, f3); FFMA2(A3a, ff, w.x); FFMA2(A3b, ff, w.y);
        }
        float4 b4 = ((const float4*)bpc)[cg];
        #pragma unroll
        for (int j = 0; j < 4; j++) {
            int nd = base + nl * 4 + j;
            if (nd >= NN) break;
            float ax, ay, az, aw;
            if      (j == 0) { UNPK2(ax, ay, A0a); UNPK2(az, aw, A0b); }
            else if (j == 1) { UNPK2(ax, ay, A1a); UNPK2(az, aw, A1b); }
            else if (j == 2) { UNPK2(ax, ay, A2a); UNPK2(az, aw, A2b); }
            else             { UNPK2(ax, ay, A3a); UNPK2(az, aw, A3b); }
            float4 o;
            o.x = ax + b4.x; o.y = ay + b4.y; o.z = az + b4.z; o.w = aw + b4.w;
            ((float4*)out)[(size_t)nd * 16 + cg] = o;
        }
    }
}

// ---------------- launch ----------------
extern "C" void kernel_launch(void* const* d_in, const int* in_sizes, int n_in,
                              void* d_out, int out_size) {
    int k = (n_in >= 17) ? 5 : 4;
    const float* lf    = (const float*)d_in[0];
    const int*   ei    = (const int*)  d_in[1];
    const float* ef    = (const float*)d_in[2];
    const float* rf    = (const float*)d_in[3];
    const float* Wlin  = (const float*)d_in[k + 0];
    const float* atts  = (const float*)d_in[k + 1];
    const float* attd  = (const float*)d_in[k + 2];
    const float* Wedge = (const float*)d_in[k + 3];
    const float* atte  = (const float*)d_in[k + 4];
    const float* bconv = (const float*)d_in[k + 5];
    const float* Wlt   = (const float*)d_in[k + 6];
    const float* blt   = (const float*)d_in[k + 7];
    const float* Wfm   = (const float*)d_in[k + 8];
    const float* bfm   = (const float*)d_in[k + 9];
    const float* Wpc   = (const float*)d_in[k + 10];
    const float* bpc   = (const float*)d_in[k + 11];
    float* out = (float*)d_out;

    int hasEi  = out_size >= NN * 64 + 2 * EE;
    int hasAtt = out_size >= NN * 64 + 2 * EE + 2 * EE;

    int nblk = (NN + 31) / 32;  // 1563
    k_vec<<<1, 256>>>(Wlin, attd, Wedge, atte);
    k_node<<<nblk, 256>>>(rf, lf, Wlin, atts);
    k_edge_alpha<<<EE / 64, 256>>>(ef, ei);
    k_alloc<<<(NN + 255) / 256, 256>>>();
    k_fill<<<(EE / 2 + 255) / 256, 256>>>(out, hasEi, hasAtt);
    k_gat<<<(NN + 7) / 8, 256>>>();
    k_dense<<<nblk, 128>>>(lf, Wlt, blt, bconv, Wfm, bfm, Wpc, bpc, out);
}

// round 15
// speedup vs baseline: 1.2415x; 1.0141x over previous
#include <cuda_runtime.h>
#include <cuda_fp16.h>

#define NN 50000
#define EE 800000

// packed f32x2 FMA (PTX-only; ptxas won't auto-fuse)
#define FFMA2(d, a, b) asm("fma.rn.f32x2 %0, %1, %2, %0;" : "+l"(d) : "l"(a), "l"(b))
#define PACK2(d, x, y) asm("mov.b64 %0, {%1, %2};" : "=l"(d) \
                           : "r"(__float_as_uint(x)), "r"(__float_as_uint(y)))
#define UNPK2(x, y, s) do { unsigned int _lo, _hi; \
    asm("mov.b64 {%0, %1}, %2;" : "=r"(_lo), "=r"(_hi) : "l"(s)); \
    (x) = __uint_as_float(_lo); (y) = __uint_as_float(_hi); } while (0)

typedef unsigned long long u64;

// ---------------- scratch ----------------
__device__ unsigned int g_xh[(size_t)NN * 64];  // x_src as half2 (128 cols)
__device__ float  g_a_src[NN * 2];
__device__ float  g_a_dst[NN * 2];
__device__ float4 g_epk [EE];                   // (exp0, exp1, src, dst) by edge id
__device__ int2   g_pk  [EE];                   // CSR payload: (src, half2 att)
__device__ float2 g_sum2[NN];                   // per-dst sum of exp
__device__ uint2  g_aggh[(size_t)NN * 32];      // aggregated messages, half2 x4
__device__ float  g_vedge[128];
__device__ float  g_udst [128];
__device__ int    g_deg [NN];
__device__ int2   g_row [NN];                   // (beg, deg)
__device__ int    g_cur [NN];
__device__ int    g_total;

// ---------------- kernels ----------------

// single block: fold attention vectors; zero the global cursor
__global__ void k_vec(const float* __restrict__ Wlin, const float* __restrict__ attd,
                      const float* __restrict__ Wedge, const float* __restrict__ atte) {
    int t = threadIdx.x;
    if (t == 0) g_total = 0;
    if (t < 128) {
        int h = t >> 6, d = t & 63;
        float acc = 0.f;
        #pragma unroll 8
        for (int c = 0; c < 64; c++) acc += Wlin[d * 128 + h * 64 + c] * attd[h * 64 + c];
        g_udst[h * 64 + d] = acc;
    } else {
        int idx = t - 128;
        int h = idx >> 6, d = idx & 63;
        float acc = 0.f;
        #pragma unroll 8
        for (int c = 0; c < 64; c++) acc += Wedge[d * 128 + h * 64 + c] * atte[h * 64 + c];
        g_vedge[h * 64 + d] = acc;
    }
}

// x_src = rf @ Wlin (fp16 out) ; a_src = x_src.att_src ; a_dst = lf.udst
// also zeroes deg/sum2 for this block's 32 nodes
__global__ void __launch_bounds__(256) k_node(
        const float* __restrict__ rf, const float* __restrict__ lf,
        const float* __restrict__ Wlin, const float* __restrict__ atts) {
    __shared__ float sF[32 * 65];
    __shared__ float sA[128], sU[128];
    int t = threadIdx.x;
    if (t < 128) { sA[t] = atts[t]; sU[t] = g_udst[t]; }
    int cg = t & 31, nl = t >> 5;
    int base = blockIdx.x * 32;
    if (t < 32) {
        int nd = base + t;
        if (nd < NN) { g_deg[nd] = 0; g_sum2[nd] = make_float2(0.f, 0.f); }
    }
    for (int i = t; i < 2048; i += 256) {
        int n = i >> 6, k = i & 63, nd = base + n;
        sF[n * 65 + k] = (nd < NN) ? rf[(size_t)nd * 64 + k] : 0.f;
    }
    __syncthreads();
    const ulonglong2* W8 = (const ulonglong2*)Wlin;
    u64 A0a = 0, A0b = 0, A1a = 0, A1b = 0, A2a = 0, A2b = 0, A3a = 0, A3b = 0;
    int r0 = (nl * 4 + 0) * 65, r1 = (nl * 4 + 1) * 65,
        r2 = (nl * 4 + 2) * 65, r3 = (nl * 4 + 3) * 65;
    #pragma unroll 8
    for (int k = 0; k < 64; k++) {
        ulonglong2 w = W8[k * 32 + cg];
        float f0 = sF[r0 + k], f1 = sF[r1 + k], f2 = sF[r2 + k], f3 = sF[r3 + k];
        u64 ff;
        PACK2(ff, f0, f0); FFMA2(A0a, ff, w.x); FFMA2(A0b, ff, w.y);
        PACK2(ff, f1, f1); FFMA2(A1a, ff, w.x); FFMA2(A1b, ff, w.y);
        PACK2(ff, f2, f2); FFMA2(A2a, ff, w.x); FFMA2(A2b, ff, w.y);
        PACK2(ff, f3, f3); FFMA2(A3a, ff, w.x); FFMA2(A3b, ff, w.y);
    }
    int h = cg >> 4, c = cg & 15;
    float4 at4 = ((const float4*)sA)[cg];
    float4 u4  = ((const float4*)sU)[h * 16 + c];
    #pragma unroll
    for (int j = 0; j < 4; j++) {
        int nd = base + nl * 4 + j;
        if (nd >= NN) break;
        float ax, ay, az, aw;
        if      (j == 0) { UNPK2(ax, ay, A0a); UNPK2(az, aw, A0b); }
        else if (j == 1) { UNPK2(ax, ay, A1a); UNPK2(az, aw, A1b); }
        else if (j == 2) { UNPK2(ax, ay, A2a); UNPK2(az, aw, A2b); }
        else             { UNPK2(ax, ay, A3a); UNPK2(az, aw, A3b); }
        __half2 h01 = __floats2half2_rn(ax, ay);
        __half2 h23 = __floats2half2_rn(az, aw);
        uint2 st;
        st.x = *reinterpret_cast<unsigned int*>(&h01);
        st.y = *reinterpret_cast<unsigned int*>(&h23);
        ((uint2*)g_xh)[(size_t)nd * 32 + cg] = st;
        float p = ax * at4.x + ay * at4.y + az * at4.z + aw * at4.w;
        float4 l4 = ((const float4*)lf)[(size_t)nd * 16 + c];
        float q = l4.x * u4.x + l4.y * u4.y + l4.z * u4.z + l4.w * u4.w;
        p += __shfl_xor_sync(0xffffffffu, p, 8);
        p += __shfl_xor_sync(0xffffffffu, p, 4);
        p += __shfl_xor_sync(0xffffffffu, p, 2);
        p += __shfl_xor_sync(0xffffffffu, p, 1);
        q += __shfl_xor_sync(0xffffffffu, q, 8);
        q += __shfl_xor_sync(0xffffffffu, q, 4);
        q += __shfl_xor_sync(0xffffffffu, q, 2);
        q += __shfl_xor_sync(0xffffffffu, q, 1);
        if (cg == 0)  { g_a_src[nd * 2 + 0] = p; g_a_dst[nd * 2 + 0] = q; }
        if (cg == 16) { g_a_src[nd * 2 + 1] = p; g_a_dst[nd * 2 + 1] = q; }
    }
}

// 4 lanes per edge: alpha -> leaky -> exp ; fat record (e0,e1,src,dst)
// vedge via __ldg (L1-resident, no smem/sync); occupancy raised to 7 blocks/SM
__global__ void __launch_bounds__(256, 7) k_edge_alpha(
        const float* __restrict__ ef, const int* __restrict__ ei) {
    int t = threadIdx.x;
    int e = blockIdx.x * 64 + (t >> 2);
    int g = t & 3;
    int src = 0, dst = 0;
    if (g == 0) { src = __ldg(&ei[e]); dst = __ldg(&ei[EE + e]); }
    const float4* E4 = (const float4*)ef;
    float4 v0 = __ldcs(&E4[(size_t)e * 16 + g]);
    float4 v1 = __ldcs(&E4[(size_t)e * 16 + g + 4]);
    float4 v2 = __ldcs(&E4[(size_t)e * 16 + g + 8]);
    float4 v3 = __ldcs(&E4[(size_t)e * 16 + g + 12]);
    float2 as = make_float2(0.f, 0.f), ad = as;
    if (g == 0) {
        as = ((const float2*)g_a_src)[src];
        ad = ((const float2*)g_a_dst)[dst];
    }
    const float4* S4 = (const float4*)g_vedge;
    float4 s0, s1;
    float p0 = 0.f, p1 = 0.f;
    s0 = __ldg(&S4[g]);      s1 = __ldg(&S4[16 + g]);
    p0 += v0.x*s0.x + v0.y*s0.y + v0.z*s0.z + v0.w*s0.w;
    p1 += v0.x*s1.x + v0.y*s1.y + v0.z*s1.z + v0.w*s1.w;
    s0 = __ldg(&S4[g + 4]);  s1 = __ldg(&S4[20 + g]);
    p0 += v1.x*s0.x + v1.y*s0.y + v1.z*s0.z + v1.w*s0.w;
    p1 += v1.x*s1.x + v1.y*s1.y + v1.z*s1.z + v1.w*s1.w;
    s0 = __ldg(&S4[g + 8]);  s1 = __ldg(&S4[24 + g]);
    p0 += v2.x*s0.x + v2.y*s0.y + v2.z*s0.z + v2.w*s0.w;
    p1 += v2.x*s1.x + v2.y*s1.y + v2.z*s1.z + v2.w*s1.w;
    s0 = __ldg(&S4[g + 12]); s1 = __ldg(&S4[28 + g]);
    p0 += v3.x*s0.x + v3.y*s0.y + v3.z*s0.z + v3.w*s0.w;
    p1 += v3.x*s1.x + v3.y*s1.y + v3.z*s1.z + v3.w*s1.w;
    float a = __shfl_xor_sync(0xffffffffu, p0, 2);
    float b = __shfl_xor_sync(0xffffffffu, p1, 2);
    float r = (g & 2) ? (p1 + b) : (p0 + a);
    r += __shfl_xor_sync(0xffffffffu, r, 1);
    float other = __shfl_xor_sync(0xffffffffu, r, 2);
    if (g == 0) {
        float a0 = as.x + ad.x + r;
        float a1 = as.y + ad.y + other;
        a0 = a0 > 0.f ? a0 : 0.2f * a0;
        a1 = a1 > 0.f ? a1 : 0.2f * a1;
        float e0 = __expf(a0), e1 = __expf(a1);
        g_epk[e] = make_float4(e0, e1, __int_as_float(src), __int_as_float(dst));
        atomicAdd(&g_deg[dst], 1);
        atomicAdd(&g_sum2[dst].x, e0);
        atomicAdd(&g_sum2[dst].y, e1);
    }
}

// CSR range allocation: block scan + one global atomic
__global__ void k_alloc() {
    __shared__ int wsum[8];
    __shared__ int sbase;
    int t = threadIdx.x;
    int i = blockIdx.x * 256 + t;
    int d = (i < NN) ? g_deg[i] : 0;
    int lane = t & 31, w = t >> 5;
    int x = d;
    #pragma unroll
    for (int o = 1; o < 32; o <<= 1) {
        int v = __shfl_up_sync(0xffffffffu, x, o);
        if (lane >= o) x += v;
    }
    if (lane == 31) wsum[w] = x;
    __syncthreads();
    if (t == 0) {
        int run = 0;
        #pragma unroll
        for (int j = 0; j < 8; j++) { int v = wsum[j]; wsum[j] = run; run += v; }
        sbase = atomicAdd(&g_total, run);
    }
    __syncthreads();
    int excl = sbase + wsum[w] + x - d;
    if (i < NN) { g_row[i] = make_int2(excl, d); g_cur[i] = excl; }
}

// CSR fill: one fat-record load; 8B packed scatter; edge_index + att coalesced
__global__ void k_fill(float* __restrict__ out, int hasEi, int hasAtt) {
    int e = blockIdx.x * blockDim.x + threadIdx.x;
    if (e >= EE) return;
    float4 rec = g_epk[e];
    int src = __float_as_int(rec.z), dst = __float_as_int(rec.w);
    float2 sm = g_sum2[dst];
    float2 att = make_float2(rec.x / (sm.x + 1e-16f), rec.y / (sm.y + 1e-16f));
    int pos = atomicAdd(&g_cur[dst], 1);
    __half2 ah = __floats2half2_rn(att.x, att.y);
    int2 pk;
    pk.x = src;
    pk.y = *reinterpret_cast<int*>(&ah);
    g_pk[pos] = pk;
    if (hasAtt)
        ((float2*)(out + (size_t)NN * 64 + 2 * EE))[e] = att;
    if (hasEi) {
        out[NN * 64 + e]      = (float)src;
        out[NN * 64 + EE + e] = (float)dst;
    }
}

// warp per dst: gather-accumulate (fp16 x_src, fp16 att), fp16 agg out
__global__ void __launch_bounds__(256) k_gat() {
    int dst  = (blockIdx.x * blockDim.x + threadIdx.x) >> 5;
    int lane = threadIdx.x & 31;
    if (dst >= NN) return;
    int2 row = g_row[dst];
    int beg = row.x, end = row.x + row.y;
    int h = lane >> 4;
    float4 acc = make_float4(0.f, 0.f, 0.f, 0.f);
    const uint2* X = (const uint2*)g_xh;
    const int2* P = g_pk;
    int i = beg;
    for (; i + 4 <= end; i += 4) {
        int2 pA = P[i], pB = P[i + 1], pC = P[i + 2], pD = P[i + 3];
        uint2 uA = X[(size_t)pA.x * 32 + lane];
        uint2 uB = X[(size_t)pB.x * 32 + lane];
        uint2 uC = X[(size_t)pC.x * 32 + lane];
        uint2 uD = X[(size_t)pD.x * 32 + lane];
        float2 tA = __half22float2(*reinterpret_cast<__half2*>(&pA.y));
        float2 tB = __half22float2(*reinterpret_cast<__half2*>(&pB.y));
        float2 tC = __half22float2(*reinterpret_cast<__half2*>(&pC.y));
        float2 tD = __half22float2(*reinterpret_cast<__half2*>(&pD.y));
        float aA = h ? tA.y : tA.x;
        float aB = h ? tB.y : tB.x;
        float aC = h ? tC.y : tC.x;
        float aD = h ? tD.y : tD.x;
        float2 x0, x1;
        x0 = __half22float2(*reinterpret_cast<__half2*>(&uA.x));
        x1 = __half22float2(*reinterpret_cast<__half2*>(&uA.y));
        acc.x += aA * x0.x; acc.y += aA * x0.y; acc.z += aA * x1.x; acc.w += aA * x1.y;
        x0 = __half22float2(*reinterpret_cast<__half2*>(&uB.x));
        x1 = __half22float2(*reinterpret_cast<__half2*>(&uB.y));
        acc.x += aB * x0.x; acc.y += aB * x0.y; acc.z += aB * x1.x; acc.w += aB * x1.y;
        x0 = __half22float2(*reinterpret_cast<__half2*>(&uC.x));
        x1 = __half22float2(*reinterpret_cast<__half2*>(&uC.y));
        acc.x += aC * x0.x; acc.y += aC * x0.y; acc.z += aC * x1.x; acc.w += aC * x1.y;
        x0 = __half22float2(*reinterpret_cast<__half2*>(&uD.x));
        x1 = __half22float2(*reinterpret_cast<__half2*>(&uD.y));
        acc.x += aD * x0.x; acc.y += aD * x0.y; acc.z += aD * x1.x; acc.w += aD * x1.y;
    }
    for (; i < end; i++) {
        int2 pA = P[i];
        float2 tA = __half22float2(*reinterpret_cast<__half2*>(&pA.y));
        float aA = h ? tA.y : tA.x;
        uint2 uA = X[(size_t)pA.x * 32 + lane];
        float2 x0 = __half22float2(*reinterpret_cast<__half2*>(&uA.x));
        float2 x1 = __half22float2(*reinterpret_cast<__half2*>(&uA.y));
        acc.x += aA * x0.x; acc.y += aA * x0.y; acc.z += aA * x1.x; acc.w += aA * x1.y;
    }
    __half2 a01 = __floats2half2_rn(acc.x, acc.y);
    __half2 a23 = __floats2half2_rn(acc.z, acc.w);
    uint2 st;
    st.x = *reinterpret_cast<unsigned int*>(&a01);
    st.y = *reinterpret_cast<unsigned int*>(&a23);
    g_aggh[(size_t)dst * 32 + lane] = st;
}

// fused dense chain; 128 thr, 32 nodes per block, FFMA2, sU aliased into sF
__global__ void __launch_bounds__(128) k_dense(
        const float* __restrict__ lf,
        const float* __restrict__ Wlt, const float* __restrict__ blt,
        const float* __restrict__ bconv,
        const float* __restrict__ Wfm, const float* __restrict__ bfm,
        const float* __restrict__ Wpc, const float* __restrict__ bpc,
        float* __restrict__ out) {
    __shared__ float sF[32 * 132];
    __shared__ float sT[32 * 68];
    __shared__ float sL[32 * 68];
    __shared__ float sbc[128];
    float* sU = sF;                       // reuse: sF dead after stage 1
    int t = threadIdx.x;
    if (t < 128) sbc[t] = bconv[t];
    int base = blockIdx.x * 32;
    __syncthreads();
    for (int i = t; i < 2048; i += 128) {
        int n = i >> 6, c2 = i & 63;
        int nd = base + n;
        float2 f = make_float2(0.f, 0.f);
        if (nd < NN) {
            unsigned int u = ((const unsigned int*)g_aggh)[(size_t)nd * 64 + c2];
            f = __half22float2(*reinterpret_cast<__half2*>(&u));
        }
        float v0 = f.x + sbc[c2 * 2], v1 = f.y + sbc[c2 * 2 + 1];
        v0 = v0 > 0.f ? v0 : 0.f;
        v1 = v1 > 0.f ? v1 : 0.f;
        *(float2*)&sF[n * 132 + c2 * 2] = make_float2(v0, v1);
    }
    for (int i = t; i < 2048; i += 128) {
        int n = i >> 6, k = i & 63, nd = base + n;
        sL[n * 68 + k] = (nd < NN) ? lf[(size_t)nd * 64 + k] : 0.f;
    }
    __syncthreads();
    int cg = t & 15, nl = t >> 4;
    int n0 = nl * 4, n1 = nl * 4 + 1, n2 = nl * 4 + 2, n3 = nl * 4 + 3;
    // ---- stage 1: K=128, Wlt -> sT ----
    {
        const ulonglong2* W8 = (const ulonglong2*)Wlt;
        u64 A0a = 0, A0b = 0, A1a = 0, A1b = 0, A2a = 0, A2b = 0, A3a = 0, A3b = 0;
        int r0 = n0 * 132, r1 = n1 * 132, r2 = n2 * 132, r3 = n3 * 132;
        #pragma unroll 8
        for (int k = 0; k < 128; k++) {
            ulonglong2 w = W8[k * 16 + cg];
            float f0 = sF[r0 + k], f1 = sF[r1 + k], f2 = sF[r2 + k], f3 = sF[r3 + k];
            u64 ff;
            PACK2(ff, f0, f0); FFMA2(A0a, ff, w.x); FFMA2(A0b, ff, w.y);
            PACK2(ff, f1, f1); FFMA2(A1a, ff, w.x); FFMA2(A1b, ff, w.y);
            PACK2(ff, f2, f2); FFMA2(A2a, ff, w.x); FFMA2(A2b, ff, w.y);
            PACK2(ff, f3, f3); FFMA2(A3a, ff, w.x); FFMA2(A3b, ff, w.y);
        }
        float4 b4 = ((const float4*)blt)[cg];
        __syncthreads();
        #pragma unroll
        for (int j = 0; j < 4; j++) {
            float ax, ay, az, aw;
            if      (j == 0) { UNPK2(ax, ay, A0a); UNPK2(az, aw, A0b); }
            else if (j == 1) { UNPK2(ax, ay, A1a); UNPK2(az, aw, A1b); }
            else if (j == 2) { UNPK2(ax, ay, A2a); UNPK2(az, aw, A2b); }
            else             { UNPK2(ax, ay, A3a); UNPK2(az, aw, A3b); }
            float4 o;
            o.x = ax + b4.x; o.y = ay + b4.y; o.z = az + b4.z; o.w = aw + b4.w;
            o.x = o.x > 0.f ? o.x : 0.f;
            o.y = o.y > 0.f ? o.y : 0.f;
            o.z = o.z > 0.f ? o.z : 0.f;
            o.w = o.w > 0.f ? o.w : 0.f;
            *(float4*)&sT[(nl * 4 + j) * 68 + cg * 4] = o;
        }
    }
    __syncthreads();
    // ---- stage 2: K=64, Wfm -> sU (aliased into sF) ----
    {
        const ulonglong2* W8 = (const ulonglong2*)Wfm;
        u64 A0a = 0, A0b = 0, A1a = 0, A1b = 0, A2a = 0, A2b = 0, A3a = 0, A3b = 0;
        int r0 = n0 * 68, r1 = n1 * 68, r2 = n2 * 68, r3 = n3 * 68;
        #pragma unroll 8
        for (int k = 0; k < 64; k++) {
            ulonglong2 w = W8[k * 16 + cg];
            float f0 = sT[r0 + k], f1 = sT[r1 + k], f2 = sT[r2 + k], f3 = sT[r3 + k];
            u64 ff;
            PACK2(ff, f0, f0); FFMA2(A0a, ff, w.x); FFMA2(A0b, ff, w.y);
            PACK2(ff, f1, f1); FFMA2(A1a, ff, w.x); FFMA2(A1b, ff, w.y);
            PACK2(ff, f2, f2); FFMA2(A2a, ff, w.x); FFMA2(A2b, ff, w.y);
            PACK2(ff, f3, f3); FFMA2(A3a, ff, w.x); FFMA2(A3b, ff, w.y);
        }
        float4 b4 = ((const float4*)bfm)[cg];
        #pragma unroll
        for (int j = 0; j < 4; j++) {
            float ax, ay, az, aw;
            if      (j == 0) { UNPK2(ax, ay, A0a); UNPK2(az, aw, A0b); }
            else if (j == 1) { UNPK2(ax, ay, A1a); UNPK2(az, aw, A1b); }
            else if (j == 2) { UNPK2(ax, ay, A2a); UNPK2(az, aw, A2b); }
            else             { UNPK2(ax, ay, A3a); UNPK2(az, aw, A3b); }
            float4 o;
            o.x = ax + b4.x; o.y = ay + b4.y; o.z = az + b4.z; o.w = aw + b4.w;
            *(float4*)&sU[(nl * 4 + j) * 68 + cg * 4] = o;
        }
    }
    __syncthreads();
    // ---- stage 3: out = sL @ Wpc[0:64] + sU @ Wpc[64:128] + bpc ----
    {
        const ulonglong2* W8 = (const ulonglong2*)Wpc;
        u64 A0a = 0, A0b = 0, A1a = 0, A1b = 0, A2a = 0, A2b = 0, A3a = 0, A3b = 0;
        int r0 = n0 * 68, r1 = n1 * 68, r2 = n2 * 68, r3 = n3 * 68;
        #pragma unroll 8
        for (int k = 0; k < 64; k++) {
            ulonglong2 w = W8[k * 16 + cg];
            float f0 = sL[r0 + k], f1 = sL[r1 + k], f2 = sL[r2 + k], f3 = sL[r3 + k];
            u64 ff;
            PACK2(ff, f0, f0); FFMA2(A0a, ff, w.x); FFMA2(A0b, ff, w.y);
            PACK2(ff, f1, f1); FFMA2(A1a, ff, w.x); FFMA2(A1b, ff, w.y);
            PACK2(ff, f2, f2); FFMA2(A2a, ff, w.x); FFMA2(A2b, ff, w.y);
            PACK2(ff, f3, f3); FFMA2(A3a, ff, w.x); FFMA2(A3b, ff, w.y);
        }
        #pragma unroll 8
        for (int k = 0; k < 64; k++) {
            ulonglong2 w = W8[(64 + k) * 16 + cg];
            float f0 = sU[r0 + k], f1 = sU[r1 + k], f2 = sU[r2 + k], f3 = sU[r3 + k];
            u64 ff;
            PACK2(ff, f0, f0); FFMA2(A0a, ff, w.x); FFMA2(A0b, ff, w.y);
            PACK2(ff, f1, f1); FFMA2(A1a, ff, w.x); FFMA2(A1b, ff, w.y);
            PACK2(ff, f2, f2); FFMA2(A2a, ff, w.x); FFMA2(A2b, ff, w.y);
            PACK2(ff, f3, f3); FFMA2(A3a, ff, w.x); FFMA2(A3b, ff, w.y);
        }
        float4 b4 = ((const float4*)bpc)[cg];
        #pragma unroll
        for (int j = 0; j < 4; j++) {
            int nd = base + nl * 4 + j;
            if (nd >= NN) break;
            float ax, ay, az, aw;
            if      (j == 0) { UNPK2(ax, ay, A0a); UNPK2(az, aw, A0b); }
            else if (j == 1) { UNPK2(ax, ay, A1a); UNPK2(az, aw, A1b); }
            else if (j == 2) { UNPK2(ax, ay, A2a); UNPK2(az, aw, A2b); }
            else             { UNPK2(ax, ay, A3a); UNPK2(az, aw, A3b); }
            float4 o;
            o.x = ax + b4.x; o.y = ay + b4.y; o.z = az + b4.z; o.w = aw + b4.w;
            ((float4*)out)[(size_t)nd * 16 + cg] = o;
        }
    }
}

// ---------------- launch ----------------
extern "C" void kernel_launch(void* const* d_in, const int* in_sizes, int n_in,
                              void* d_out, int out_size) {
    int k = (n_in >= 17) ? 5 : 4;
    const float* lf    = (const float*)d_in[0];
    const int*   ei    = (const int*)  d_in[1];
    const float* ef    = (const float*)d_in[2];
    const float* rf    = (const float*)d_in[3];
    const float* Wlin  = (const float*)d_in[k + 0];
    const float* atts  = (const float*)d_in[k + 1];
    const float* attd  = (const float*)d_in[k + 2];
    const float* Wedge = (const float*)d_in[k + 3];
    const float* atte  = (const float*)d_in[k + 4];
    const float* bconv = (const float*)d_in[k + 5];
    const float* Wlt   = (const float*)d_in[k + 6];
    const float* blt   = (const float*)d_in[k + 7];
    const float* Wfm   = (const float*)d_in[k + 8];
    const float* bfm   = (const float*)d_in[k + 9];
    const float* Wpc   = (const float*)d_in[k + 10];
    const float* bpc   = (const float*)d_in[k + 11];
    float* out = (float*)d_out;

    int hasEi  = out_size >= NN * 64 + 2 * EE;
    int hasAtt = out_size >= NN * 64 + 2 * EE + 2 * EE;

    int nblk = (NN + 31) / 32;  // 1563
    k_vec<<<1, 256>>>(Wlin, attd, Wedge, atte);
    k_node<<<nblk, 256>>>(rf, lf, Wlin, atts);
    k_edge_alpha<<<EE / 64, 256>>>(ef, ei);
    k_alloc<<<(NN + 255) / 256, 256>>>();
    k_fill<<<(EE + 255) / 256, 256>>>(out, hasEi, hasAtt);
    k_gat<<<(NN + 7) / 8, 256>>>();
    k_dense<<<nblk, 128>>>(lf, Wlt, blt, bconv, Wfm, bfm, Wpc, bpc, out);
}

// round 16
// speedup vs baseline: 1.2627x; 1.0171x over previous
#include <cuda_runtime.h>
#include <cuda_fp16.h>

#define NN 50000
#define EE 800000

// packed f32x2 FMA (PTX-only; ptxas won't auto-fuse)
#define FFMA2(d, a, b) asm("fma.rn.f32x2 %0, %1, %2, %0;" : "+l"(d) : "l"(a), "l"(b))
#define PACK2(d, x, y) asm("mov.b64 %0, {%1, %2};" : "=l"(d) \
                           : "r"(__float_as_uint(x)), "r"(__float_as_uint(y)))
#define UNPK2(x, y, s) do { unsigned int _lo, _hi; \
    asm("mov.b64 {%0, %1}, %2;" : "=r"(_lo), "=r"(_hi) : "l"(s)); \
    (x) = __uint_as_float(_lo); (y) = __uint_as_float(_hi); } while (0)

typedef unsigned long long u64;

// ---------------- scratch ----------------
__device__ unsigned int g_xh[(size_t)NN * 64];  // x_src as half2 (128 cols)
__device__ float  g_a_src[NN * 2];
__device__ float  g_a_dst[NN * 2];
__device__ float4 g_epk [EE];                   // (exp0, exp1, src, dst) by edge id
__device__ int2   g_pk  [EE];                   // CSR payload: (src, half2 att)
__device__ float2 g_sum2[NN];                   // per-dst sum of exp
__device__ uint2  g_aggh[(size_t)NN * 32];      // aggregated messages, half2 x4
__device__ float  g_vedge[128];
__device__ float  g_udst [128];
__device__ int    g_deg [NN];
__device__ int2   g_row [NN];                   // (beg, deg)
__device__ int    g_cur [NN];
__device__ int    g_total;

// ---------------- kernels ----------------

// single block: fold attention vectors; zero the global cursor
__global__ void k_vec(const float* __restrict__ Wlin, const float* __restrict__ attd,
                      const float* __restrict__ Wedge, const float* __restrict__ atte) {
    int t = threadIdx.x;
    if (t == 0) g_total = 0;
    if (t < 128) {
        int h = t >> 6, d = t & 63;
        float acc = 0.f;
        #pragma unroll 8
        for (int c = 0; c < 64; c++) acc += Wlin[d * 128 + h * 64 + c] * attd[h * 64 + c];
        g_udst[h * 64 + d] = acc;
    } else {
        int idx = t - 128;
        int h = idx >> 6, d = idx & 63;
        float acc = 0.f;
        #pragma unroll 8
        for (int c = 0; c < 64; c++) acc += Wedge[d * 128 + h * 64 + c] * atte[h * 64 + c];
        g_vedge[h * 64 + d] = acc;
    }
}

// x_src = rf @ Wlin (fp16 out) ; a_src = x_src.att_src ; a_dst = lf.udst
// also zeroes deg/sum2 for this block's 32 nodes
__global__ void __launch_bounds__(256) k_node(
        const float* __restrict__ rf, const float* __restrict__ lf,
        const float* __restrict__ Wlin, const float* __restrict__ atts) {
    __shared__ float sF[32 * 65];
    __shared__ float sA[128], sU[128];
    int t = threadIdx.x;
    if (t < 128) { sA[t] = atts[t]; sU[t] = g_udst[t]; }
    int cg = t & 31, nl = t >> 5;
    int base = blockIdx.x * 32;
    if (t < 32) {
        int nd = base + t;
        if (nd < NN) { g_deg[nd] = 0; g_sum2[nd] = make_float2(0.f, 0.f); }
    }
    for (int i = t; i < 2048; i += 256) {
        int n = i >> 6, k = i & 63, nd = base + n;
        sF[n * 65 + k] = (nd < NN) ? rf[(size_t)nd * 64 + k] : 0.f;
    }
    __syncthreads();
    const ulonglong2* W8 = (const ulonglong2*)Wlin;
    u64 A0a = 0, A0b = 0, A1a = 0, A1b = 0, A2a = 0, A2b = 0, A3a = 0, A3b = 0;
    int r0 = (nl * 4 + 0) * 65, r1 = (nl * 4 + 1) * 65,
        r2 = (nl * 4 + 2) * 65, r3 = (nl * 4 + 3) * 65;
    #pragma unroll 8
    for (int k = 0; k < 64; k++) {
        ulonglong2 w = W8[k * 32 + cg];
        float f0 = sF[r0 + k], f1 = sF[r1 + k], f2 = sF[r2 + k], f3 = sF[r3 + k];
        u64 ff;
        PACK2(ff, f0, f0); FFMA2(A0a, ff, w.x); FFMA2(A0b, ff, w.y);
        PACK2(ff, f1, f1); FFMA2(A1a, ff, w.x); FFMA2(A1b, ff, w.y);
        PACK2(ff, f2, f2); FFMA2(A2a, ff, w.x); FFMA2(A2b, ff, w.y);
        PACK2(ff, f3, f3); FFMA2(A3a, ff, w.x); FFMA2(A3b, ff, w.y);
    }
    int h = cg >> 4, c = cg & 15;
    float4 at4 = ((const float4*)sA)[cg];
    float4 u4  = ((const float4*)sU)[h * 16 + c];
    #pragma unroll
    for (int j = 0; j < 4; j++) {
        int nd = base + nl * 4 + j;
        if (nd >= NN) break;
        float ax, ay, az, aw;
        if      (j == 0) { UNPK2(ax, ay, A0a); UNPK2(az, aw, A0b); }
        else if (j == 1) { UNPK2(ax, ay, A1a); UNPK2(az, aw, A1b); }
        else if (j == 2) { UNPK2(ax, ay, A2a); UNPK2(az, aw, A2b); }
        else             { UNPK2(ax, ay, A3a); UNPK2(az, aw, A3b); }
        __half2 h01 = __floats2half2_rn(ax, ay);
        __half2 h23 = __floats2half2_rn(az, aw);
        uint2 st;
        st.x = *reinterpret_cast<unsigned int*>(&h01);
        st.y = *reinterpret_cast<unsigned int*>(&h23);
        ((uint2*)g_xh)[(size_t)nd * 32 + cg] = st;
        float p = ax * at4.x + ay * at4.y + az * at4.z + aw * at4.w;
        float4 l4 = ((const float4*)lf)[(size_t)nd * 16 + c];
        float q = l4.x * u4.x + l4.y * u4.y + l4.z * u4.z + l4.w * u4.w;
        p += __shfl_xor_sync(0xffffffffu, p, 8);
        p += __shfl_xor_sync(0xffffffffu, p, 4);
        p += __shfl_xor_sync(0xffffffffu, p, 2);
        p += __shfl_xor_sync(0xffffffffu, p, 1);
        q += __shfl_xor_sync(0xffffffffu, q, 8);
        q += __shfl_xor_sync(0xffffffffu, q, 4);
        q += __shfl_xor_sync(0xffffffffu, q, 2);
        q += __shfl_xor_sync(0xffffffffu, q, 1);
        if (cg == 0)  { g_a_src[nd * 2 + 0] = p; g_a_dst[nd * 2 + 0] = q; }
        if (cg == 16) { g_a_src[nd * 2 + 1] = p; g_a_dst[nd * 2 + 1] = q; }
    }
}

// 4 lanes per edge: alpha -> leaky -> exp ; writes fat record (e0,e1,src,dst)
__global__ void __launch_bounds__(256) k_edge_alpha(
        const float* __restrict__ ef, const int* __restrict__ ei) {
    __shared__ float sv[128];
    int t = threadIdx.x;
    int e = blockIdx.x * 64 + (t >> 2);
    int g = t & 3;
    int src = 0, dst = 0;
    if (g == 0) { src = __ldg(&ei[e]); dst = __ldg(&ei[EE + e]); }
    if (t < 128) sv[t] = g_vedge[t];
    const float4* E4 = (const float4*)ef;
    float4 v0 = __ldcs(&E4[(size_t)e * 16 + g]);
    float4 v1 = __ldcs(&E4[(size_t)e * 16 + g + 4]);
    float4 v2 = __ldcs(&E4[(size_t)e * 16 + g + 8]);
    float4 v3 = __ldcs(&E4[(size_t)e * 16 + g + 12]);
    __syncthreads();
    float2 as = make_float2(0.f, 0.f), ad = as;
    if (g == 0) {
        as = ((const float2*)g_a_src)[src];
        ad = ((const float2*)g_a_dst)[dst];
    }
    const float4* S4 = (const float4*)sv;
    float4 s0, s1;
    float p0 = 0.f, p1 = 0.f;
    s0 = S4[g];      s1 = S4[16 + g];
    p0 += v0.x*s0.x + v0.y*s0.y + v0.z*s0.z + v0.w*s0.w;
    p1 += v0.x*s1.x + v0.y*s1.y + v0.z*s1.z + v0.w*s1.w;
    s0 = S4[g + 4];  s1 = S4[20 + g];
    p0 += v1.x*s0.x + v1.y*s0.y + v1.z*s0.z + v1.w*s0.w;
    p1 += v1.x*s1.x + v1.y*s1.y + v1.z*s1.z + v1.w*s1.w;
    s0 = S4[g + 8];  s1 = S4[24 + g];
    p0 += v2.x*s0.x + v2.y*s0.y + v2.z*s0.z + v2.w*s0.w;
    p1 += v2.x*s1.x + v2.y*s1.y + v2.z*s1.z + v2.w*s1.w;
    s0 = S4[g + 12]; s1 = S4[28 + g];
    p0 += v3.x*s0.x + v3.y*s0.y + v3.z*s0.z + v3.w*s0.w;
    p1 += v3.x*s1.x + v3.y*s1.y + v3.z*s1.z + v3.w*s1.w;
    float a = __shfl_xor_sync(0xffffffffu, p0, 2);
    float b = __shfl_xor_sync(0xffffffffu, p1, 2);
    float r = (g & 2) ? (p1 + b) : (p0 + a);
    r += __shfl_xor_sync(0xffffffffu, r, 1);
    float other = __shfl_xor_sync(0xffffffffu, r, 2);
    if (g == 0) {
        float a0 = as.x + ad.x + r;
        float a1 = as.y + ad.y + other;
        a0 = a0 > 0.f ? a0 : 0.2f * a0;
        a1 = a1 > 0.f ? a1 : 0.2f * a1;
        float e0 = __expf(a0), e1 = __expf(a1);
        g_epk[e] = make_float4(e0, e1, __int_as_float(src), __int_as_float(dst));
        atomicAdd(&g_deg[dst], 1);
        atomicAdd(&g_sum2[dst].x, e0);
        atomicAdd(&g_sum2[dst].y, e1);
    }
}

// CSR range allocation: block scan + one global atomic
__global__ void k_alloc() {
    __shared__ int wsum[8];
    __shared__ int sbase;
    int t = threadIdx.x;
    int i = blockIdx.x * 256 + t;
    int d = (i < NN) ? g_deg[i] : 0;
    int lane = t & 31, w = t >> 5;
    int x = d;
    #pragma unroll
    for (int o = 1; o < 32; o <<= 1) {
        int v = __shfl_up_sync(0xffffffffu, x, o);
        if (lane >= o) x += v;
    }
    if (lane == 31) wsum[w] = x;
    __syncthreads();
    if (t == 0) {
        int run = 0;
        #pragma unroll
        for (int j = 0; j < 8; j++) { int v = wsum[j]; wsum[j] = run; run += v; }
        sbase = atomicAdd(&g_total, run);
    }
    __syncthreads();
    int excl = sbase + wsum[w] + x - d;
    if (i < NN) { g_row[i] = make_int2(excl, d); g_cur[i] = excl; }
}

// CSR fill: one fat-record streaming load; 8B packed scatter; outputs coalesced
__global__ void k_fill(float* __restrict__ out, int hasEi, int hasAtt) {
    int e = blockIdx.x * blockDim.x + threadIdx.x;
    if (e >= EE) return;
    float4 rec = __ldcs(&g_epk[e]);
    int src = __float_as_int(rec.z), dst = __float_as_int(rec.w);
    float2 sm = g_sum2[dst];
    float2 att = make_float2(rec.x / (sm.x + 1e-16f), rec.y / (sm.y + 1e-16f));
    int pos = atomicAdd(&g_cur[dst], 1);
    __half2 ah = __floats2half2_rn(att.x, att.y);
    int2 pk;
    pk.x = src;
    pk.y = *reinterpret_cast<int*>(&ah);
    g_pk[pos] = pk;
    if (hasAtt)
        ((float2*)(out + (size_t)NN * 64 + 2 * EE))[e] = att;
    if (hasEi) {
        out[NN * 64 + e]      = (float)src;
        out[NN * 64 + EE + e] = (float)dst;
    }
}

// warp per dst: gather-accumulate (fp16 x_src, fp16 att), unroll 8 for MLP
__global__ void __launch_bounds__(256) k_gat() {
    int dst  = (blockIdx.x * blockDim.x + threadIdx.x) >> 5;
    int lane = threadIdx.x & 31;
    if (dst >= NN) return;
    int2 row = g_row[dst];
    int beg = row.x, end = row.x + row.y;
    int h = lane >> 4;
    float4 acc = make_float4(0.f, 0.f, 0.f, 0.f);
    const uint2* X = (const uint2*)g_xh;
    const int2* P = g_pk;
    int i = beg;
    for (; i + 8 <= end; i += 8) {
        int2 p0 = P[i],     p1 = P[i + 1], p2 = P[i + 2], p3 = P[i + 3];
        int2 p4 = P[i + 4], p5 = P[i + 5], p6 = P[i + 6], p7 = P[i + 7];
        uint2 u0 = X[(size_t)p0.x * 32 + lane];
        uint2 u1 = X[(size_t)p1.x * 32 + lane];
        uint2 u2 = X[(size_t)p2.x * 32 + lane];
        uint2 u3 = X[(size_t)p3.x * 32 + lane];
        uint2 u4 = X[(size_t)p4.x * 32 + lane];
        uint2 u5 = X[(size_t)p5.x * 32 + lane];
        uint2 u6 = X[(size_t)p6.x * 32 + lane];
        uint2 u7 = X[(size_t)p7.x * 32 + lane];
        #pragma unroll
        for (int j = 0; j < 8; j++) {
            int2  pj = (j==0)?p0:(j==1)?p1:(j==2)?p2:(j==3)?p3:(j==4)?p4:(j==5)?p5:(j==6)?p6:p7;
            uint2 uj = (j==0)?u0:(j==1)?u1:(j==2)?u2:(j==3)?u3:(j==4)?u4:(j==5)?u5:(j==6)?u6:u7;
            float2 tj = __half22float2(*reinterpret_cast<__half2*>(&pj.y));
            float aj = h ? tj.y : tj.x;
            float2 x0 = __half22float2(*reinterpret_cast<__half2*>(&uj.x));
            float2 x1 = __half22float2(*reinterpret_cast<__half2*>(&uj.y));
            acc.x += aj * x0.x; acc.y += aj * x0.y;
            acc.z += aj * x1.x; acc.w += aj * x1.y;
        }
    }
    for (; i + 4 <= end; i += 4) {
        int2 p0 = P[i], p1 = P[i + 1], p2 = P[i + 2], p3 = P[i + 3];
        uint2 u0 = X[(size_t)p0.x * 32 + lane];
        uint2 u1 = X[(size_t)p1.x * 32 + lane];
        uint2 u2 = X[(size_t)p2.x * 32 + lane];
        uint2 u3 = X[(size_t)p3.x * 32 + lane];
        #pragma unroll
        for (int j = 0; j < 4; j++) {
            int2  pj = (j==0)?p0:(j==1)?p1:(j==2)?p2:p3;
            uint2 uj = (j==0)?u0:(j==1)?u1:(j==2)?u2:u3;
            float2 tj = __half22float2(*reinterpret_cast<__half2*>(&pj.y));
            float aj = h ? tj.y : tj.x;
            float2 x0 = __half22float2(*reinterpret_cast<__half2*>(&uj.x));
            float2 x1 = __half22float2(*reinterpret_cast<__half2*>(&uj.y));
            acc.x += aj * x0.x; acc.y += aj * x0.y;
            acc.z += aj * x1.x; acc.w += aj * x1.y;
        }
    }
    for (; i < end; i++) {
        int2 pA = P[i];
        float2 tA = __half22float2(*reinterpret_cast<__half2*>(&pA.y));
        float aA = h ? tA.y : tA.x;
        uint2 uA = X[(size_t)pA.x * 32 + lane];
        float2 x0 = __half22float2(*reinterpret_cast<__half2*>(&uA.x));
        float2 x1 = __half22float2(*reinterpret_cast<__half2*>(&uA.y));
        acc.x += aA * x0.x; acc.y += aA * x0.y; acc.z += aA * x1.x; acc.w += aA * x1.y;
    }
    __half2 a01 = __floats2half2_rn(acc.x, acc.y);
    __half2 a23 = __floats2half2_rn(acc.z, acc.w);
    uint2 st;
    st.x = *reinterpret_cast<unsigned int*>(&a01);
    st.y = *reinterpret_cast<unsigned int*>(&a23);
    g_aggh[(size_t)dst * 32 + lane] = st;
}

// fused dense chain; 128 thr, 32 nodes per block, FFMA2, sU aliased into sF
__global__ void __launch_bounds__(128) k_dense(
        const float* __restrict__ lf,
        const float* __restrict__ Wlt, const float* __restrict__ blt,
        const float* __restrict__ bconv,
        const float* __restrict__ Wfm, const float* __restrict__ bfm,
        const float* __restrict__ Wpc, const float* __restrict__ bpc,
        float* __restrict__ out) {
    __shared__ float sF[32 * 132];
    __shared__ float sT[32 * 68];
    __shared__ float sL[32 * 68];
    __shared__ float sbc[128];
    float* sU = sF;                       // reuse: sF dead after stage 1
    int t = threadIdx.x;
    if (t < 128) sbc[t] = bconv[t];
    int base = blockIdx.x * 32;
    __syncthreads();
    for (int i = t; i < 2048; i += 128) {
        int n = i >> 6, c2 = i & 63;
        int nd = base + n;
        float2 f = make_float2(0.f, 0.f);
        if (nd < NN) {
            unsigned int u = ((const unsigned int*)g_aggh)[(size_t)nd * 64 + c2];
            f = __half22float2(*reinterpret_cast<__half2*>(&u));
        }
        float v0 = f.x + sbc[c2 * 2], v1 = f.y + sbc[c2 * 2 + 1];
        v0 = v0 > 0.f ? v0 : 0.f;
        v1 = v1 > 0.f ? v1 : 0.f;
        *(float2*)&sF[n * 132 + c2 * 2] = make_float2(v0, v1);
    }
    for (int i = t; i < 2048; i += 128) {
        int n = i >> 6, k = i & 63, nd = base + n;
        sL[n * 68 + k] = (nd < NN) ? lf[(size_t)nd * 64 + k] : 0.f;
    }
    __syncthreads();
    int cg = t & 15, nl = t >> 4;
    int n0 = nl * 4, n1 = nl * 4 + 1, n2 = nl * 4 + 2, n3 = nl * 4 + 3;
    // ---- stage 1: K=128, Wlt -> sT ----
    {
        const ulonglong2* W8 = (const ulonglong2*)Wlt;
        u64 A0a = 0, A0b = 0, A1a = 0, A1b = 0, A2a = 0, A2b = 0, A3a = 0, A3b = 0;
        int r0 = n0 * 132, r1 = n1 * 132, r2 = n2 * 132, r3 = n3 * 132;
        #pragma unroll 8
        for (int k = 0; k < 128; k++) {
            ulonglong2 w = W8[k * 16 + cg];
            float f0 = sF[r0 + k], f1 = sF[r1 + k], f2 = sF[r2 + k], f3 = sF[r3 + k];
            u64 ff;
            PACK2(ff, f0, f0); FFMA2(A0a, ff, w.x); FFMA2(A0b, ff, w.y);
            PACK2(ff, f1, f1); FFMA2(A1a, ff, w.x); FFMA2(A1b, ff, w.y);
            PACK2(ff, f2, f2); FFMA2(A2a, ff, w.x); FFMA2(A2b, ff, w.y);
            PACK2(ff, f3, f3); FFMA2(A3a, ff, w.x); FFMA2(A3b, ff, w.y);
        }
        float4 b4 = ((const float4*)blt)[cg];
        __syncthreads();
        #pragma unroll
        for (int j = 0; j < 4; j++) {
            float ax, ay, az, aw;
            if      (j == 0) { UNPK2(ax, ay, A0a); UNPK2(az, aw, A0b); }
            else if (j == 1) { UNPK2(ax, ay, A1a); UNPK2(az, aw, A1b); }
            else if (j == 2) { UNPK2(ax, ay, A2a); UNPK2(az, aw, A2b); }
            else             { UNPK2(ax, ay, A3a); UNPK2(az, aw, A3b); }
            float4 o;
            o.x = ax + b4.x; o.y = ay + b4.y; o.z = az + b4.z; o.w = aw + b4.w;
            o.x = o.x > 0.f ? o.x : 0.f;
            o.y = o.y > 0.f ? o.y : 0.f;
            o.z = o.z > 0.f ? o.z : 0.f;
            o.w = o.w > 0.f ? o.w : 0.f;
            *(float4*)&sT[(nl * 4 + j) * 68 + cg * 4] = o;
        }
    }
    __syncthreads();
    // ---- stage 2: K=64, Wfm -> sU (aliased into sF) ----
    {
        const ulonglong2* W8 = (const ulonglong2*)Wfm;
        u64 A0a = 0, A0b = 0, A1a = 0, A1b = 0, A2a = 0, A2b = 0, A3a = 0, A3b = 0;
        int r0 = n0 * 68, r1 = n1 * 68, r2 = n2 * 68, r3 = n3 * 68;
        #pragma unroll 8
        for (int k = 0; k < 64; k++) {
            ulonglong2 w = W8[k * 16 + cg];
            float f0 = sT[r0 + k], f1 = sT[r1 + k], f2 = sT[r2 + k], f3 = sT[r3 + k];
            u64 ff;
            PACK2(ff, f0, f0); FFMA2(A0a, ff, w.x); FFMA2(A0b, ff, w.y);
            PACK2(ff, f1, f1); FFMA2(A1a, ff, w.x); FFMA2(A1b, ff, w.y);
            PACK2(ff, f2, f2); FFMA2(A2a, ff, w.x); FFMA2(A2b, ff, w.y);
            PACK2(ff, f3, f3); FFMA2(A3a, ff, w.x); FFMA2(A3b, ff, w.y);
        }
        float4 b4 = ((const float4*)bfm)[cg];
        #pragma unroll
        for (int j = 0; j < 4; j++) {
            float ax, ay, az, aw;
            if      (j == 0) { UNPK2(ax, ay, A0a); UNPK2(az, aw, A0b); }
            else if (j == 1) { UNPK2(ax, ay, A1a); UNPK2(az, aw, A1b); }
            else if (j == 2) { UNPK2(ax, ay, A2a); UNPK2(az, aw, A2b); }
            else             { UNPK2(ax, ay, A3a); UNPK2(az, aw, A3b); }
            float4 o;
            o.x = ax + b4.x; o.y = ay + b4.y; o.z = az + b4.z; o.w = aw + b4.w;
            *(float4*)&sU[(nl * 4 + j) * 68 + cg * 4] = o;
        }
    }
    __syncthreads();
    // ---- stage 3: out = sL @ Wpc[0:64] + sU @ Wpc[64:128] + bpc ----
    {
        const ulonglong2* W8 = (const ulonglong2*)Wpc;
        u64 A0a = 0, A0b = 0, A1a = 0, A1b = 0, A2a = 0, A2b = 0, A3a = 0, A3b = 0;
        int r0 = n0 * 68, r1 = n1 * 68, r2 = n2 * 68, r3 = n3 * 68;
        #pragma unroll 8
        for (int k = 0; k < 64; k++) {
            ulonglong2 w = W8[k * 16 + cg];
            float f0 = sL[r0 + k], f1 = sL[r1 + k], f2 = sL[r2 + k], f3 = sL[r3 + k];
            u64 ff;
            PACK2(ff, f0, f0); FFMA2(A0a, ff, w.x); FFMA2(A0b, ff, w.y);
            PACK2(ff, f1, f1); FFMA2(A1a, ff, w.x); FFMA2(A1b, ff, w.y);
            PACK2(ff, f2, f2); FFMA2(A2a, ff, w.x); FFMA2(A2b, ff, w.y);
            PACK2(ff, f3, f3); FFMA2(A3a, ff, w.x); FFMA2(A3b, ff, w.y);
        }
        #pragma unroll 8
        for (int k = 0; k < 64; k++) {
            ulonglong2 w = W8[(64 + k) * 16 + cg];
            float f0 = sU[r0 + k], f1 = sU[r1 + k], f2 = sU[r2 + k], f3 = sU[r3 + k];
            u64 ff;
            PACK2(ff, f0, f0); FFMA2(A0a, ff, w.x); FFMA2(A0b, ff, w.y);
            PACK2(ff, f1, f1); FFMA2(A1a, ff, w.x); FFMA2(A1b, ff, w.y);
            PACK2(ff, f2, f2); FFMA2(A2a, ff, w.x); FFMA2(A2b, ff, w.y);
            PACK2(ff, f3, f3); FFMA2(A3a, ff, w.x); FFMA2(A3b, ff, w.y);
        }
        float4 b4 = ((const float4*)bpc)[cg];
        #pragma unroll
        for (int j = 0; j < 4; j++) {
            int nd = base + nl * 4 + j;
            if (nd >= NN) break;
            float ax, ay, az, aw;
            if      (j == 0) { UNPK2(ax, ay, A0a); UNPK2(az, aw, A0b); }
            else if (j == 1) { UNPK2(ax, ay, A1a); UNPK2(az, aw, A1b); }
            else if (j == 2) { UNPK2(ax, ay, A2a); UNPK2(az, aw, A2b); }
            else             { UNPK2(ax, ay, A3a); UNPK2(az, aw, A3b); }
            float4 o;
            o.x = ax + b4.x; o.y = ay + b4.y; o.z = az + b4.z; o.w = aw + b4.w;
            ((float4*)out)[(size_t)nd * 16 + cg] = o;
        }
    }
}

// ---------------- launch ----------------
extern "C" void kernel_launch(void* const* d_in, const int* in_sizes, int n_in,
                              void* d_out, int out_size) {
    int k = (n_in >= 17) ? 5 : 4;
    const float* lf    = (const float*)d_in[0];
    const int*   ei    = (const int*)  d_in[1];
    const float* ef    = (const float*)d_in[2];
    const float* rf    = (const float*)d_in[3];
    const float* Wlin  = (const float*)d_in[k + 0];
    const float* atts  = (const float*)d_in[k + 1];
    const float* attd  = (const float*)d_in[k + 2];
    const float* Wedge = (const float*)d_in[k + 3];
    const float* atte  = (const float*)d_in[k + 4];
    const float* bconv = (const float*)d_in[k + 5];
    const float* Wlt   = (const float*)d_in[k + 6];
    const float* blt   = (const float*)d_in[k + 7];
    const float* Wfm   = (const float*)d_in[k + 8];
    const float* bfm   = (const float*)d_in[k + 9];
    const float* Wpc   = (const float*)d_in[k + 10];
    const float* bpc   = (const float*)d_in[k + 11];
    float* out = (float*)d_out;

    int hasEi  = out_size >= NN * 64 + 2 * EE;
    int hasAtt = out_size >= NN * 64 + 2 * EE + 2 * EE;

    int nblk = (NN + 31) / 32;  // 1563
    k_vec<<<1, 256>>>(Wlin, attd, Wedge, atte);
    k_node<<<nblk, 256>>>(rf, lf, Wlin, atts);
    k_edge_alpha<<<EE / 64, 256>>>(ef, ei);
    k_alloc<<<(NN + 255) / 256, 256>>>();
    k_fill<<<(EE + 255) / 256, 256>>>(out, hasEi, hasAtt);
    k_gat<<<(NN + 7) / 8, 256>>>();
    k_dense<<<nblk, 128>>>(lf, Wlt, blt, bconv, Wfm, bfm, Wpc, bpc, out);
}

// round 17
// speedup vs baseline: 1.2957x; 1.0261x over previous
#include <cuda_runtime.h>
#include <cuda_fp16.h>

#define NN 50000
#define EE 800000

// packed f32x2 FMA (PTX-only; ptxas won't auto-fuse)
#define FFMA2(d, a, b) asm("fma.rn.f32x2 %0, %1, %2, %0;" : "+l"(d) : "l"(a), "l"(b))
#define PACK2(d, x, y) asm("mov.b64 %0, {%1, %2};" : "=l"(d) \
                           : "r"(__float_as_uint(x)), "r"(__float_as_uint(y)))
#define UNPK2(x, y, s) do { unsigned int _lo, _hi; \
    asm("mov.b64 {%0, %1}, %2;" : "=r"(_lo), "=r"(_hi) : "l"(s)); \
    (x) = __uint_as_float(_lo); (y) = __uint_as_float(_hi); } while (0)

// PDL: block until predecessor grid's memory is visible (required with
// programmatic stream serialization). sm_90+.
#define GDC_WAIT() asm volatile("griddepcontrol.wait;" ::: "memory")

typedef unsigned long long u64;

// ---------------- scratch ----------------
__device__ unsigned int g_xh[(size_t)NN * 64];  // x_src as half2 (128 cols)
__device__ float  g_a_src[NN * 2];
__device__ float  g_a_dst[NN * 2];
__device__ float4 g_epk [EE];                   // (exp0, exp1, src, dst) by edge id
__device__ int2   g_pk  [EE];                   // CSR payload: (src, half2 att)
__device__ float2 g_sum2[NN];                   // per-dst sum of exp
__device__ uint2  g_aggh[(size_t)NN * 32];      // aggregated messages, half2 x4
__device__ float  g_vedge[128];
__device__ float  g_udst [128];
__device__ int    g_deg [NN];
__device__ int2   g_row [NN];                   // (beg, deg)
__device__ int    g_cur [NN];
__device__ int    g_total;

// ---------------- kernels ----------------

// single block: fold attention vectors; zero the global cursor
__global__ void k_vec(const float* __restrict__ Wlin, const float* __restrict__ attd,
                      const float* __restrict__ Wedge, const float* __restrict__ atte) {
    GDC_WAIT();
    int t = threadIdx.x;
    if (t == 0) g_total = 0;
    if (t < 128) {
        int h = t >> 6, d = t & 63;
        float acc = 0.f;
        #pragma unroll 8
        for (int c = 0; c < 64; c++) acc += Wlin[d * 128 + h * 64 + c] * attd[h * 64 + c];
        g_udst[h * 64 + d] = acc;
    } else {
        int idx = t - 128;
        int h = idx >> 6, d = idx & 63;
        float acc = 0.f;
        #pragma unroll 8
        for (int c = 0; c < 64; c++) acc += Wedge[d * 128 + h * 64 + c] * atte[h * 64 + c];
        g_vedge[h * 64 + d] = acc;
    }
}

// x_src = rf @ Wlin (fp16 out) ; a_src = x_src.att_src ; a_dst = lf.udst
// also zeroes deg/sum2 for this block's 32 nodes
__global__ void __launch_bounds__(256) k_node(
        const float* __restrict__ rf, const float* __restrict__ lf,
        const float* __restrict__ Wlin, const float* __restrict__ atts) {
    GDC_WAIT();
    __shared__ float sF[32 * 65];
    __shared__ float sA[128], sU[128];
    int t = threadIdx.x;
    if (t < 128) { sA[t] = atts[t]; sU[t] = g_udst[t]; }
    int cg = t & 31, nl = t >> 5;
    int base = blockIdx.x * 32;
    if (t < 32) {
        int nd = base + t;
        if (nd < NN) { g_deg[nd] = 0; g_sum2[nd] = make_float2(0.f, 0.f); }
    }
    for (int i = t; i < 2048; i += 256) {
        int n = i >> 6, k = i & 63, nd = base + n;
        sF[n * 65 + k] = (nd < NN) ? rf[(size_t)nd * 64 + k] : 0.f;
    }
    __syncthreads();
    const ulonglong2* W8 = (const ulonglong2*)Wlin;
    u64 A0a = 0, A0b = 0, A1a = 0, A1b = 0, A2a = 0, A2b = 0, A3a = 0, A3b = 0;
    int r0 = (nl * 4 + 0) * 65, r1 = (nl * 4 + 1) * 65,
        r2 = (nl * 4 + 2) * 65, r3 = (nl * 4 + 3) * 65;
    #pragma unroll 8
    for (int k = 0; k < 64; k++) {
        ulonglong2 w = W8[k * 32 + cg];
        float f0 = sF[r0 + k], f1 = sF[r1 + k], f2 = sF[r2 + k], f3 = sF[r3 + k];
        u64 ff;
        PACK2(ff, f0, f0); FFMA2(A0a, ff, w.x); FFMA2(A0b, ff, w.y);
        PACK2(ff, f1, f1); FFMA2(A1a, ff, w.x); FFMA2(A1b, ff, w.y);
        PACK2(ff, f2, f2); FFMA2(A2a, ff, w.x); FFMA2(A2b, ff, w.y);
        PACK2(ff, f3, f3); FFMA2(A3a, ff, w.x); FFMA2(A3b, ff, w.y);
    }
    int h = cg >> 4, c = cg & 15;
    float4 at4 = ((const float4*)sA)[cg];
    float4 u4  = ((const float4*)sU)[h * 16 + c];
    #pragma unroll
    for (int j = 0; j < 4; j++) {
        int nd = base + nl * 4 + j;
        if (nd >= NN) break;
        float ax, ay, az, aw;
        if      (j == 0) { UNPK2(ax, ay, A0a); UNPK2(az, aw, A0b); }
        else if (j == 1) { UNPK2(ax, ay, A1a); UNPK2(az, aw, A1b); }
        else if (j == 2) { UNPK2(ax, ay, A2a); UNPK2(az, aw, A2b); }
        else             { UNPK2(ax, ay, A3a); UNPK2(az, aw, A3b); }
        __half2 h01 = __floats2half2_rn(ax, ay);
        __half2 h23 = __floats2half2_rn(az, aw);
        uint2 st;
        st.x = *reinterpret_cast<unsigned int*>(&h01);
        st.y = *reinterpret_cast<unsigned int*>(&h23);
        ((uint2*)g_xh)[(size_t)nd * 32 + cg] = st;
        float p = ax * at4.x + ay * at4.y + az * at4.z + aw * at4.w;
        float4 l4 = ((const float4*)lf)[(size_t)nd * 16 + c];
        float q = l4.x * u4.x + l4.y * u4.y + l4.z * u4.z + l4.w * u4.w;
        p += __shfl_xor_sync(0xffffffffu, p, 8);
        p += __shfl_xor_sync(0xffffffffu, p, 4);
        p += __shfl_xor_sync(0xffffffffu, p, 2);
        p += __shfl_xor_sync(0xffffffffu, p, 1);
        q += __shfl_xor_sync(0xffffffffu, q, 8);
        q += __shfl_xor_sync(0xffffffffu, q, 4);
        q += __shfl_xor_sync(0xffffffffu, q, 2);
        q += __shfl_xor_sync(0xffffffffu, q, 1);
        if (cg == 0)  { g_a_src[nd * 2 + 0] = p; g_a_dst[nd * 2 + 0] = q; }
        if (cg == 16) { g_a_src[nd * 2 + 1] = p; g_a_dst[nd * 2 + 1] = q; }
    }
}

// 4 lanes per edge: alpha -> leaky -> exp ; writes fat record (e0,e1,src,dst)
__global__ void __launch_bounds__(256) k_edge_alpha(
        const float* __restrict__ ef, const int* __restrict__ ei) {
    GDC_WAIT();
    __shared__ float sv[128];
    int t = threadIdx.x;
    int e = blockIdx.x * 64 + (t >> 2);
    int g = t & 3;
    int src = 0, dst = 0;
    if (g == 0) { src = __ldg(&ei[e]); dst = __ldg(&ei[EE + e]); }
    if (t < 128) sv[t] = g_vedge[t];
    const float4* E4 = (const float4*)ef;
    float4 v0 = __ldcs(&E4[(size_t)e * 16 + g]);
    float4 v1 = __ldcs(&E4[(size_t)e * 16 + g + 4]);
    float4 v2 = __ldcs(&E4[(size_t)e * 16 + g + 8]);
    float4 v3 = __ldcs(&E4[(size_t)e * 16 + g + 12]);
    __syncthreads();
    float2 as = make_float2(0.f, 0.f), ad = as;
    if (g == 0) {
        as = ((const float2*)g_a_src)[src];
        ad = ((const float2*)g_a_dst)[dst];
    }
    const float4* S4 = (const float4*)sv;
    float4 s0, s1;
    float p0 = 0.f, p1 = 0.f;
    s0 = S4[g];      s1 = S4[16 + g];
    p0 += v0.x*s0.x + v0.y*s0.y + v0.z*s0.z + v0.w*s0.w;
    p1 += v0.x*s1.x + v0.y*s1.y + v0.z*s1.z + v0.w*s1.w;
    s0 = S4[g + 4];  s1 = S4[20 + g];
    p0 += v1.x*s0.x + v1.y*s0.y + v1.z*s0.z + v1.w*s0.w;
    p1 += v1.x*s1.x + v1.y*s1.y + v1.z*s1.z + v1.w*s1.w;
    s0 = S4[g + 8];  s1 = S4[24 + g];
    p0 += v2.x*s0.x + v2.y*s0.y + v2.z*s0.z + v2.w*s0.w;
    p1 += v2.x*s1.x + v2.y*s1.y + v2.z*s1.z + v2.w*s1.w;
    s0 = S4[g + 12]; s1 = S4[28 + g];
    p0 += v3.x*s0.x + v3.y*s0.y + v3.z*s0.z + v3.w*s0.w;
    p1 += v3.x*s1.x + v3.y*s1.y + v3.z*s1.z + v3.w*s1.w;
    float a = __shfl_xor_sync(0xffffffffu, p0, 2);
    float b = __shfl_xor_sync(0xffffffffu, p1, 2);
    float r = (g & 2) ? (p1 + b) : (p0 + a);
    r += __shfl_xor_sync(0xffffffffu, r, 1);
    float other = __shfl_xor_sync(0xffffffffu, r, 2);
    if (g == 0) {
        float a0 = as.x + ad.x + r;
        float a1 = as.y + ad.y + other;
        a0 = a0 > 0.f ? a0 : 0.2f * a0;
        a1 = a1 > 0.f ? a1 : 0.2f * a1;
        float e0 = __expf(a0), e1 = __expf(a1);
        g_epk[e] = make_float4(e0, e1, __int_as_float(src), __int_as_float(dst));
        atomicAdd(&g_deg[dst], 1);
        atomicAdd(&g_sum2[dst].x, e0);
        atomicAdd(&g_sum2[dst].y, e1);
    }
}

// CSR range allocation: block scan + one global atomic
__global__ void k_alloc() {
    GDC_WAIT();
    __shared__ int wsum[8];
    __shared__ int sbase;
    int t = threadIdx.x;
    int i = blockIdx.x * 256 + t;
    int d = (i < NN) ? g_deg[i] : 0;
    int lane = t & 31, w = t >> 5;
    int x = d;
    #pragma unroll
    for (int o = 1; o < 32; o <<= 1) {
        int v = __shfl_up_sync(0xffffffffu, x, o);
        if (lane >= o) x += v;
    }
    if (lane == 31) wsum[w] = x;
    __syncthreads();
    if (t == 0) {
        int run = 0;
        #pragma unroll
        for (int j = 0; j < 8; j++) { int v = wsum[j]; wsum[j] = run; run += v; }
        sbase = atomicAdd(&g_total, run);
    }
    __syncthreads();
    int excl = sbase + wsum[w] + x - d;
    if (i < NN) { g_row[i] = make_int2(excl, d); g_cur[i] = excl; }
}

// CSR fill: one fat-record streaming load; 8B packed scatter; outputs coalesced
__global__ void k_fill(float* __restrict__ out, int hasEi, int hasAtt) {
    GDC_WAIT();
    int e = blockIdx.x * blockDim.x + threadIdx.x;
    if (e >= EE) return;
    float4 rec = __ldcs(&g_epk[e]);
    int src = __float_as_int(rec.z), dst = __float_as_int(rec.w);
    float2 sm = g_sum2[dst];
    float2 att = make_float2(rec.x / (sm.x + 1e-16f), rec.y / (sm.y + 1e-16f));
    int pos = atomicAdd(&g_cur[dst], 1);
    __half2 ah = __floats2half2_rn(att.x, att.y);
    int2 pk;
    pk.x = src;
    pk.y = *reinterpret_cast<int*>(&ah);
    g_pk[pos] = pk;
    if (hasAtt)
        ((float2*)(out + (size_t)NN * 64 + 2 * EE))[e] = att;
    if (hasEi) {
        out[NN * 64 + e]      = (float)src;
        out[NN * 64 + EE + e] = (float)dst;
    }
}

// warp per dst: gather-accumulate (fp16 x_src, fp16 att), unroll 8 for MLP
__global__ void __launch_bounds__(256) k_gat() {
    GDC_WAIT();
    int dst  = (blockIdx.x * blockDim.x + threadIdx.x) >> 5;
    int lane = threadIdx.x & 31;
    if (dst >= NN) return;
    int2 row = g_row[dst];
    int beg = row.x, end = row.x + row.y;
    int h = lane >> 4;
    float4 acc = make_float4(0.f, 0.f, 0.f, 0.f);
    const uint2* X = (const uint2*)g_xh;
    const int2* P = g_pk;
    int i = beg;
    for (; i + 8 <= end; i += 8) {
        int2 p0 = P[i],     p1 = P[i + 1], p2 = P[i + 2], p3 = P[i + 3];
        int2 p4 = P[i + 4], p5 = P[i + 5], p6 = P[i + 6], p7 = P[i + 7];
        uint2 u0 = X[(size_t)p0.x * 32 + lane];
        uint2 u1 = X[(size_t)p1.x * 32 + lane];
        uint2 u2 = X[(size_t)p2.x * 32 + lane];
        uint2 u3 = X[(size_t)p3.x * 32 + lane];
        uint2 u4 = X[(size_t)p4.x * 32 + lane];
        uint2 u5 = X[(size_t)p5.x * 32 + lane];
        uint2 u6 = X[(size_t)p6.x * 32 + lane];
        uint2 u7 = X[(size_t)p7.x * 32 + lane];
        #pragma unroll
        for (int j = 0; j < 8; j++) {
            int2  pj = (j==0)?p0:(j==1)?p1:(j==2)?p2:(j==3)?p3:(j==4)?p4:(j==5)?p5:(j==6)?p6:p7;
            uint2 uj = (j==0)?u0:(j==1)?u1:(j==2)?u2:(j==3)?u3:(j==4)?u4:(j==5)?u5:(j==6)?u6:u7;
            float2 tj = __half22float2(*reinterpret_cast<__half2*>(&pj.y));
            float aj = h ? tj.y : tj.x;
            float2 x0 = __half22float2(*reinterpret_cast<__half2*>(&uj.x));
            float2 x1 = __half22float2(*reinterpret_cast<__half2*>(&uj.y));
            acc.x += aj * x0.x; acc.y += aj * x0.y;
            acc.z += aj * x1.x; acc.w += aj * x1.y;
        }
    }
    for (; i + 4 <= end; i += 4) {
        int2 p0 = P[i], p1 = P[i + 1], p2 = P[i + 2], p3 = P[i + 3];
        uint2 u0 = X[(size_t)p0.x * 32 + lane];
        uint2 u1 = X[(size_t)p1.x * 32 + lane];
        uint2 u2 = X[(size_t)p2.x * 32 + lane];
        uint2 u3 = X[(size_t)p3.x * 32 + lane];
        #pragma unroll
        for (int j = 0; j < 4; j++) {
            int2  pj = (j==0)?p0:(j==1)?p1:(j==2)?p2:p3;
            uint2 uj = (j==0)?u0:(j==1)?u1:(j==2)?u2:u3;
            float2 tj = __half22float2(*reinterpret_cast<__half2*>(&pj.y));
            float aj = h ? tj.y : tj.x;
            float2 x0 = __half22float2(*reinterpret_cast<__half2*>(&uj.x));
            float2 x1 = __half22float2(*reinterpret_cast<__half2*>(&uj.y));
            acc.x += aj * x0.x; acc.y += aj * x0.y;
            acc.z += aj * x1.x; acc.w += aj * x1.y;
        }
    }
    for (; i < end; i++) {
        int2 pA = P[i];
        float2 tA = __half22float2(*reinterpret_cast<__half2*>(&pA.y));
        float aA = h ? tA.y : tA.x;
        uint2 uA = X[(size_t)pA.x * 32 + lane];
        float2 x0 = __half22float2(*reinterpret_cast<__half2*>(&uA.x));
        float2 x1 = __half22float2(*reinterpret_cast<__half2*>(&uA.y));
        acc.x += aA * x0.x; acc.y += aA * x0.y; acc.z += aA * x1.x; acc.w += aA * x1.y;
    }
    __half2 a01 = __floats2half2_rn(acc.x, acc.y);
    __half2 a23 = __floats2half2_rn(acc.z, acc.w);
    uint2 st;
    st.x = *reinterpret_cast<unsigned int*>(&a01);
    st.y = *reinterpret_cast<unsigned int*>(&a23);
    g_aggh[(size_t)dst * 32 + lane] = st;
}

// fused dense chain; 128 thr, 32 nodes per block, FFMA2, sU aliased into sF
__global__ void __launch_bounds__(128) k_dense(
        const float* __restrict__ lf,
        const float* __restrict__ Wlt, const float* __restrict__ blt,
        const float* __restrict__ bconv,
        const float* __restrict__ Wfm, const float* __restrict__ bfm,
        const float* __restrict__ Wpc, const float* __restrict__ bpc,
        float* __restrict__ out) {
    GDC_WAIT();
    __shared__ float sF[32 * 132];
    __shared__ float sT[32 * 68];
    __shared__ float sL[32 * 68];
    __shared__ float sbc[128];
    float* sU = sF;                       // reuse: sF dead after stage 1
    int t = threadIdx.x;
    if (t < 128) sbc[t] = bconv[t];
    int base = blockIdx.x * 32;
    __syncthreads();
    for (int i = t; i < 2048; i += 128) {
        int n = i >> 6, c2 = i & 63;
        int nd = base + n;
        float2 f = make_float2(0.f, 0.f);
        if (nd < NN) {
            unsigned int u = ((const unsigned int*)g_aggh)[(size_t)nd * 64 + c2];
            f = __half22float2(*reinterpret_cast<__half2*>(&u));
        }
        float v0 = f.x + sbc[c2 * 2], v1 = f.y + sbc[c2 * 2 + 1];
        v0 = v0 > 0.f ? v0 : 0.f;
        v1 = v1 > 0.f ? v1 : 0.f;
        *(float2*)&sF[n * 132 + c2 * 2] = make_float2(v0, v1);
    }
    for (int i = t; i < 2048; i += 128) {
        int n = i >> 6, k = i & 63, nd = base + n;
        sL[n * 68 + k] = (nd < NN) ? lf[(size_t)nd * 64 + k] : 0.f;
    }
    __syncthreads();
    int cg = t & 15, nl = t >> 4;
    int n0 = nl * 4, n1 = nl * 4 + 1, n2 = nl * 4 + 2, n3 = nl * 4 + 3;
    // ---- stage 1: K=128, Wlt -> sT ----
    {
        const ulonglong2* W8 = (const ulonglong2*)Wlt;
        u64 A0a = 0, A0b = 0, A1a = 0, A1b = 0, A2a = 0, A2b = 0, A3a = 0, A3b = 0;
        int r0 = n0 * 132, r1 = n1 * 132, r2 = n2 * 132, r3 = n3 * 132;
        #pragma unroll 8
        for (int k = 0; k < 128; k++) {
            ulonglong2 w = W8[k * 16 + cg];
            float f0 = sF[r0 + k], f1 = sF[r1 + k], f2 = sF[r2 + k], f3 = sF[r3 + k];
            u64 ff;
            PACK2(ff, f0, f0); FFMA2(A0a, ff, w.x); FFMA2(A0b, ff, w.y);
            PACK2(ff, f1, f1); FFMA2(A1a, ff, w.x); FFMA2(A1b, ff, w.y);
            PACK2(ff, f2, f2); FFMA2(A2a, ff, w.x); FFMA2(A2b, ff, w.y);
            PACK2(ff, f3, f3); FFMA2(A3a, ff, w.x); FFMA2(A3b, ff, w.y);
        }
        float4 b4 = ((const float4*)blt)[cg];
        __syncthreads();
        #pragma unroll
        for (int j = 0; j < 4; j++) {
            float ax, ay, az, aw;
            if      (j == 0) { UNPK2(ax, ay, A0a); UNPK2(az, aw, A0b); }
            else if (j == 1) { UNPK2(ax, ay, A1a); UNPK2(az, aw, A1b); }
            else if (j == 2) { UNPK2(ax, ay, A2a); UNPK2(az, aw, A2b); }
            else             { UNPK2(ax, ay, A3a); UNPK2(az, aw, A3b); }
            float4 o;
            o.x = ax + b4.x; o.y = ay + b4.y; o.z = az + b4.z; o.w = aw + b4.w;
            o.x = o.x > 0.f ? o.x : 0.f;
            o.y = o.y > 0.f ? o.y : 0.f;
            o.z = o.z > 0.f ? o.z : 0.f;
            o.w = o.w > 0.f ? o.w : 0.f;
            *(float4*)&sT[(nl * 4 + j) * 68 + cg * 4] = o;
        }
    }
    __syncthreads();
    // ---- stage 2: K=64, Wfm -> sU (aliased into sF) ----
    {
        const ulonglong2* W8 = (const ulonglong2*)Wfm;
        u64 A0a = 0, A0b = 0, A1a = 0, A1b = 0, A2a = 0, A2b = 0, A3a = 0, A3b = 0;
        int r0 = n0 * 68, r1 = n1 * 68, r2 = n2 * 68, r3 = n3 * 68;
        #pragma unroll 8
        for (int k = 0; k < 64; k++) {
            ulonglong2 w = W8[k * 16 + cg];
            float f0 = sT[r0 + k], f1 = sT[r1 + k], f2 = sT[r2 + k], f3 = sT[r3 + k];
            u64 ff;
            PACK2(ff, f0, f0); FFMA2(A0a, ff, w.x); FFMA2(A0b, ff, w.y);
            PACK2(ff, f1, f1); FFMA2(A1a, ff, w.x); FFMA2(A1b, ff, w.y);
            PACK2(ff, f2, f2); FFMA2(A2a, ff, w.x); FFMA2(A2b, ff, w.y);
            PACK2(ff, f3, f3); FFMA2(A3a, ff, w.x); FFMA2(A3b, ff, w.y);
        }
        float4 b4 = ((const float4*)bfm)[cg];
        #pragma unroll
        for (int j = 0; j < 4; j++) {
            float ax, ay, az, aw;
            if      (j == 0) { UNPK2(ax, ay, A0a); UNPK2(az, aw, A0b); }
            else if (j == 1) { UNPK2(ax, ay, A1a); UNPK2(az, aw, A1b); }
            else if (j == 2) { UNPK2(ax, ay, A2a); UNPK2(az, aw, A2b); }
            else             { UNPK2(ax, ay, A3a); UNPK2(az, aw, A3b); }
            float4 o;
            o.x = ax + b4.x; o.y = ay + b4.y; o.z = az + b4.z; o.w = aw + b4.w;
            *(float4*)&sU[(nl * 4 + j) * 68 + cg * 4] = o;
        }
    }
    __syncthreads();
    // ---- stage 3: out = sL @ Wpc[0:64] + sU @ Wpc[64:128] + bpc ----
    {
        const ulonglong2* W8 = (const ulonglong2*)Wpc;
        u64 A0a = 0, A0b = 0, A1a = 0, A1b = 0, A2a = 0, A2b = 0, A3a = 0, A3b = 0;
        int r0 = n0 * 68, r1 = n1 * 68, r2 = n2 * 68, r3 = n3 * 68;
        #pragma unroll 8
        for (int k = 0; k < 64; k++) {
            ulonglong2 w = W8[k * 16 + cg];
            float f0 = sL[r0 + k], f1 = sL[r1 + k], f2 = sL[r2 + k], f3 = sL[r3 + k];
            u64 ff;
            PACK2(ff, f0, f0); FFMA2(A0a, ff, w.x); FFMA2(A0b, ff, w.y);
            PACK2(ff, f1, f1); FFMA2(A1a, ff, w.x); FFMA2(A1b, ff, w.y);
            PACK2(ff, f2, f2); FFMA2(A2a, ff, w.x); FFMA2(A2b, ff, w.y);
            PACK2(ff, f3, f3); FFMA2(A3a, ff, w.x); FFMA2(A3b, ff, w.y);
        }
        #pragma unroll 8
        for (int k = 0; k < 64; k++) {
            ulonglong2 w = W8[(64 + k) * 16 + cg];
            float f0 = sU[r0 + k], f1 = sU[r1 + k], f2 = sU[r2 + k], f3 = sU[r3 + k];
            u64 ff;
            PACK2(ff, f0, f0); FFMA2(A0a, ff, w.x); FFMA2(A0b, ff, w.y);
            PACK2(ff, f1, f1); FFMA2(A1a, ff, w.x); FFMA2(A1b, ff, w.y);
            PACK2(ff, f2, f2); FFMA2(A2a, ff, w.x); FFMA2(A2b, ff, w.y);
            PACK2(ff, f3, f3); FFMA2(A3a, ff, w.x); FFMA2(A3b, ff, w.y);
        }
        float4 b4 = ((const float4*)bpc)[cg];
        #pragma unroll
        for (int j = 0; j < 4; j++) {
            int nd = base + nl * 4 + j;
            if (nd >= NN) break;
            float ax, ay, az, aw;
            if      (j == 0) { UNPK2(ax, ay, A0a); UNPK2(az, aw, A0b); }
            else if (j == 1) { UNPK2(ax, ay, A1a); UNPK2(az, aw, A1b); }
            else if (j == 2) { UNPK2(ax, ay, A2a); UNPK2(az, aw, A2b); }
            else             { UNPK2(ax, ay, A3a); UNPK2(az, aw, A3b); }
            float4 o;
            o.x = ax + b4.x; o.y = ay + b4.y; o.z = az + b4.z; o.w = aw + b4.w;
            ((float4*)out)[(size_t)nd * 16 + cg] = o;
        }
    }
}

// ---------------- launch (PDL: pre-stage dependent grids) ----------------
#define LAUNCH_PDL(K, GRID, BLOCK, ...) do {                                  \
    cudaLaunchConfig_t _cfg = {};                                             \
    _cfg.gridDim = dim3(GRID); _cfg.blockDim = dim3(BLOCK);                   \
    _cfg.dynamicSmemBytes = 0; _cfg.stream = 0;                               \
    cudaLaunchAttribute _at[1];                                               \
    _at[0].id = cudaLaunchAttributeProgrammaticStreamSerialization;           \
    _at[0].val.programmaticStreamSerializationAllowed = 1;                    \
    _cfg.attrs = _at; _cfg.numAttrs = 1;                                      \
    cudaLaunchKernelEx(&_cfg, K, ##__VA_ARGS__);                              \
} while (0)

extern "C" void kernel_launch(void* const* d_in, const int* in_sizes, int n_in,
                              void* d_out, int out_size) {
    int k = (n_in >= 17) ? 5 : 4;
    const float* lf    = (const float*)d_in[0];
    const int*   ei    = (const int*)  d_in[1];
    const float* ef    = (const float*)d_in[2];
    const float* rf    = (const float*)d_in[3];
    const float* Wlin  = (const float*)d_in[k + 0];
    const float* atts  = (const float*)d_in[k + 1];
    const float* attd  = (const float*)d_in[k + 2];
    const float* Wedge = (const float*)d_in[k + 3];
    const float* atte  = (const float*)d_in[k + 4];
    const float* bconv = (const float*)d_in[k + 5];
    const float* Wlt   = (const float*)d_in[k + 6];
    const float* blt   = (const float*)d_in[k + 7];
    const float* Wfm   = (const float*)d_in[k + 8];
    const float* bfm   = (const float*)d_in[k + 9];
    const float* Wpc   = (const float*)d_in[k + 10];
    const float* bpc   = (const float*)d_in[k + 11];
    float* out = (float*)d_out;

    int hasEi  = out_size >= NN * 64 + 2 * EE;
    int hasAtt = out_size >= NN * 64 + 2 * EE + 2 * EE;

    int nblk = (NN + 31) / 32;  // 1563
    LAUNCH_PDL(k_vec, 1, 256, Wlin, attd, Wedge, atte);
    LAUNCH_PDL(k_node, nblk, 256, rf, lf, Wlin, atts);
    LAUNCH_PDL(k_edge_alpha, EE / 64, 256, ef, ei);
    LAUNCH_PDL(k_alloc, (NN + 255) / 256, 256);
    LAUNCH_PDL(k_fill, (EE + 255) / 256, 256, out, hasEi, hasAtt);
    LAUNCH_PDL(k_gat, (NN + 7) / 8, 256);
    LAUNCH_PDL(k_dense, nblk, 128, lf, Wlt, blt, bconv, Wfm, bfm, Wpc, bpc, out);
}